// round 9
// baseline (speedup 1.0000x reference)
#include <cuda_runtime.h>
#include <cuda_fp16.h>
#include <math.h>

// GPTClosedLoop: 128-step closed-loop rollout of a tiny GPT.
// B=32, T_H=128, NR=1, L=6, D=128, H=4, DH=32.
//
// KV-cache incremental decode, one CTA per batch. fp16 weight staging.
// Round 8: register prefetch of every weight/KV wave one phase ahead
// (loads issued before the barrier that publishes their activations),
// all small params preloaded to SMEM. Arithmetic order preserved vs R7.

#define BATCH    32
#define TH       128
#define DMODEL   128
#define NLAYER   6
#define NHEAD    4
#define DH       32
#define NTHREADS 512

// KV cache: K [b][l][dim][token], V [b][l][token][dim]
__device__ float g_k[BATCH * NLAYER * DMODEL * TH];
__device__ float g_v[BATCH * NLAYER * TH * DMODEL];

// fp16 weight stages
__device__ __half g_qkv_h [NLAYER * 128 * 384];
__device__ __half g_proj_h[NLAYER * 128 * 128];
__device__ __half g_fc_h  [NLAYER * 128 * 512];
__device__ __half g_fc2_h [NLAYER * 512 * 128];

__global__ void cvt_qkv (const float* __restrict__ s){ int i = blockIdx.x*1024+threadIdx.x; if (i < NLAYER*128*384) g_qkv_h [i] = __float2half_rn(s[i]); }
__global__ void cvt_proj(const float* __restrict__ s){ int i = blockIdx.x*1024+threadIdx.x; if (i < NLAYER*128*128) g_proj_h[i] = __float2half_rn(s[i]); }
__global__ void cvt_fc  (const float* __restrict__ s){ int i = blockIdx.x*1024+threadIdx.x; if (i < NLAYER*128*512) g_fc_h  [i] = __float2half_rn(s[i]); }
__global__ void cvt_fc2 (const float* __restrict__ s){ int i = blockIdx.x*1024+threadIdx.x; if (i < NLAYER*512*128) g_fc2_h [i] = __float2half_rn(s[i]); }

// SMEM layout (floats)
#define OFF_WPE   0                    // 128*128
#define OFF_QKVB  (OFF_WPE  + 16384)   // 6*384
#define OFF_FCB   (OFF_QKVB + 2304)    // 6*512
#define OFF_PROJB (OFF_FCB  + 3072)    // 6*128
#define OFF_FC2B  (OFF_PROJB+ 768)     // 6*128
#define OFF_LN1W  (OFF_FC2B + 768)     // 6*128
#define OFF_LN1B  (OFF_LN1W + 768)
#define OFF_LN2W  (OFF_LN1B + 768)
#define OFF_LN2B  (OFF_LN2W + 768)
#define OFF_LNFW  (OFF_LN2B + 768)     // 128
#define OFF_LNFB  (OFF_LNFW + 128)
#define OFF_HEADW (OFF_LNFB + 128)
#define OFF_WTEW  (OFF_HEADW+ 128)     // 256
#define OFF_WTEB  (OFF_WTEW + 256)     // 128
#define OFF_RS    (OFF_WTEB + 128)     // 128
#define OFF_XB    (OFF_RS   + 128)
#define OFF_HB    (OFF_XB   + 128)
#define OFF_QB    (OFF_HB   + 128)
#define OFF_OB    (OFF_QB   + 128)
#define OFF_KCUR  (OFF_OB   + 128)
#define OFF_VCUR  (OFF_KCUR + 128)
#define OFF_ATT   (OFF_VCUR + 128)     // 512
#define OFF_GB    (OFF_ATT  + 512)     // 512
#define OFF_RED   (OFF_GB   + 512)     // 4096
#define OFF_WRED  (OFF_RED  + 4096)    // 32
#define OFF_SCAL  (OFF_WRED + 32)      // 4
#define SMEM_FLOATS (OFF_SCAL + 4)

__device__ __forceinline__ void block_layernorm(
    const float* __restrict__ in, float* __restrict__ outb,
    const float* __restrict__ w, const float* __restrict__ b,
    float* wred, int tid)
{
    float v = (tid < 128) ? in[tid] : 0.f;
    float s1 = v, s2 = v * v;
    #pragma unroll
    for (int o = 16; o > 0; o >>= 1) {
        s1 += __shfl_xor_sync(0xffffffffu, s1, o);
        s2 += __shfl_xor_sync(0xffffffffu, s2, o);
    }
    if ((tid & 31) == 0) { wred[tid >> 5] = s1; wred[16 + (tid >> 5)] = s2; }
    __syncthreads();
    float m   = (wred[0] + wred[1] + wred[2] + wred[3]) * (1.f / 128.f);
    float ex2 = (wred[16] + wred[17] + wred[18] + wred[19]) * (1.f / 128.f);
    float rstd = rsqrtf(ex2 - m * m + 1e-5f);
    if (tid < 128) outb[tid] = (v - m) * rstd * w[tid] + b[tid];
    __syncthreads();
}

__global__ __launch_bounds__(NTHREADS, 1)
void gpt_rollout_kernel(
    const float* __restrict__ data,
    const float* __restrict__ r,
    const float* __restrict__ wte_w,  const float* __restrict__ wte_b,
    const float* __restrict__ wpe,
    const float* __restrict__ ln1_w,  const float* __restrict__ ln1_b,
    const float* __restrict__ ln2_w,  const float* __restrict__ ln2_b,
    const float* __restrict__ qkv_b,
    const float* __restrict__ proj_b,
    const float* __restrict__ fc_b,
    const float* __restrict__ fc2_b,
    const float* __restrict__ lnf_w,  const float* __restrict__ lnf_b,
    const float* __restrict__ head_w, const float* __restrict__ head_b,
    float* __restrict__ out)
{
    extern __shared__ float sm[];
    float* wpe_s   = sm + OFF_WPE;
    float* qkvb_s  = sm + OFF_QKVB;
    float* fcb_s   = sm + OFF_FCB;
    float* projb_s = sm + OFF_PROJB;
    float* fc2b_s  = sm + OFF_FC2B;
    float* ln1w_s  = sm + OFF_LN1W;
    float* ln1b_s  = sm + OFF_LN1B;
    float* ln2w_s  = sm + OFF_LN2W;
    float* ln2b_s  = sm + OFF_LN2B;
    float* lnfw_s  = sm + OFF_LNFW;
    float* lnfb_s  = sm + OFF_LNFB;
    float* headw_s = sm + OFF_HEADW;
    float* wtew_s  = sm + OFF_WTEW;
    float* wteb_s  = sm + OFF_WTEB;
    float* rs      = sm + OFF_RS;
    float* xb      = sm + OFF_XB;
    float* hb      = sm + OFF_HB;
    float* qb      = sm + OFF_QB;
    float* ob      = sm + OFF_OB;
    float* kcur    = sm + OFF_KCUR;
    float* vcur    = sm + OFF_VCUR;
    float* att     = sm + OFF_ATT;
    float* gb      = sm + OFF_GB;
    float* red     = sm + OFF_RED;
    float* wred    = sm + OFF_WRED;
    float* scal    = sm + OFF_SCAL;

    const int b   = blockIdx.x;
    const int tid = threadIdx.x;

    const float p0 = data[b * 2 + 0];
    const float p1 = data[b * 2 + 1];

    // ----- one-time preload of all small params into SMEM -----
    for (int idx = tid; idx < 16384; idx += NTHREADS) wpe_s[idx]  = wpe[idx];
    for (int idx = tid; idx < 2304;  idx += NTHREADS) qkvb_s[idx] = qkv_b[idx];
    for (int idx = tid; idx < 3072;  idx += NTHREADS) fcb_s[idx]  = fc_b[idx];
    for (int idx = tid; idx < 768;   idx += NTHREADS) {
        projb_s[idx] = proj_b[idx];
        fc2b_s[idx]  = fc2_b[idx];
        ln1w_s[idx]  = ln1_w[idx];
        ln1b_s[idx]  = ln1_b[idx];
        ln2w_s[idx]  = ln2_w[idx];
        ln2b_s[idx]  = ln2_b[idx];
    }
    if (tid < 128) {
        lnfw_s[tid]  = lnf_w[tid];
        lnfb_s[tid]  = lnf_b[tid];
        headw_s[tid] = head_w[tid];
        wteb_s[tid]  = wte_b[tid];
        rs[tid]      = r[b * TH + tid];
    }
    if (tid < 256) wtew_s[tid] = wte_w[tid];
    if (tid == 0) { scal[0] = 0.f; scal[1] = 0.f; scal[2] = head_b[0]; }
    __syncthreads();

    for (int i = 0; i < TH; i++) {
        const float s_cur  = scal[0];
        const float u_prev = scal[1];
        if (tid == 0) out[b * TH + i] = s_cur;
        const float e = rs[i] - s_cur;

        if (tid < 128) {
            xb[tid] = e * wtew_s[tid] + u_prev * wtew_s[128 + tid]
                      + wteb_s[tid] + wpe_s[i * 128 + tid];
        }
        __syncthreads();

        for (int l = 0; l < NLAYER; l++) {
            float* kbase = g_k + (size_t)(b * NLAYER + l) * DMODEL * TH;
            float* vbase = g_v + (size_t)(b * NLAYER + l) * TH * DMODEL;

            // === prefetch qkv weights (hidden behind ln1) ===
            uint4 wq[16];
            const int sq = tid / 48, gq = tid % 48;
            if (tid < 384) {
                const __half* W = g_qkv_h + l * (128 * 384) + (sq * 16) * 384 + gq * 8;
                #pragma unroll
                for (int d = 0; d < 16; d++) wq[d] = *(const uint4*)(W + d * 384);
            }

            // ----- ln1 -----
            block_layernorm(xb, hb, ln1w_s + l * 128, ln1b_s + l * 128, wred, tid);

            // ----- qkv FMA (same splits as R7: 8 K-segs x 48 col-groups) -----
            if (tid < 384) {
                const float* hp = hb + sq * 16;
                float a0=0,a1=0,a2=0,a3=0,a4=0,a5=0,a6=0,a7=0;
                #pragma unroll
                for (int d = 0; d < 16; d++) {
                    float h = hp[d];
                    const __half2* h2 = reinterpret_cast<const __half2*>(&wq[d]);
                    float2 f0 = __half22float2(h2[0]);
                    float2 f1 = __half22float2(h2[1]);
                    float2 f2 = __half22float2(h2[2]);
                    float2 f3 = __half22float2(h2[3]);
                    a0 += h*f0.x; a1 += h*f0.y; a2 += h*f1.x; a3 += h*f1.y;
                    a4 += h*f2.x; a5 += h*f2.y; a6 += h*f3.x; a7 += h*f3.y;
                }
                float4* rp = (float4*)(red + sq * 384 + gq * 8);
                rp[0] = make_float4(a0, a1, a2, a3);
                rp[1] = make_float4(a4, a5, a6, a7);
            }

            // === prefetch K/V cache rows j<i (hidden behind qkv reduce) ===
            const int hh = tid >> 7;        // head (logits role)
            const int jj = tid & 127;       // key position (logits role)
            float kv[32];
            {
                const float* kp = kbase + (hh * DH) * TH + jj;
                #pragma unroll
                for (int d = 0; d < 32; d++)
                    kv[d] = (jj < i) ? kp[d * TH] : 0.f;
            }
            const int s4 = tid >> 7, dim = tid & 127, j0 = s4 * 32;  // AV role
            float vv[32];
            {
                const float* vp = vbase + dim;
                #pragma unroll
                for (int t = 0; t < 32; t++)
                    vv[t] = (j0 + t < i) ? vp[(j0 + t) * DMODEL] : 0.f;
            }
            __syncthreads();

            // ----- qkv reduce -> q / K,V (global + SMEM stash) -----
            if (tid < 384) {
                float acc = qkvb_s[l * 384 + tid];
                #pragma unroll
                for (int s = 0; s < 8; s++) acc += red[s * 384 + tid];
                if (tid < 128)      qb[tid] = acc;
                else if (tid < 256) { kbase[(tid - 128) * TH + i] = acc; kcur[tid - 128] = acc; }
                else                { vbase[i * DMODEL + (tid - 256)] = acc; vcur[tid - 256] = acc; }
            }
            __syncthreads();

            // ----- attention logits (registers + SMEM only) -----
            float logit;
            {
                const bool valid = (jj <= i);
                float dot = 0.f;
                #pragma unroll
                for (int d = 0; d < DH; d += 4) {
                    float4 qv = *(const float4*)(qb + hh * DH + d);
                    float k0 = (jj < i) ? kv[d + 0] : kcur[hh * DH + d + 0];
                    float k1 = (jj < i) ? kv[d + 1] : kcur[hh * DH + d + 1];
                    float k2 = (jj < i) ? kv[d + 2] : kcur[hh * DH + d + 2];
                    float k3 = (jj < i) ? kv[d + 3] : kcur[hh * DH + d + 3];
                    dot += qv.x * k0 + qv.y * k1 + qv.z * k2 + qv.w * k3;
                }
                logit = valid ? dot * 0.17677669529663689f : -3.0e38f;
            }

            // === prefetch proj weights (hidden behind softmax) ===
            uint4 wp[4];
            {
                const int sp = tid >> 4, gp = tid & 15;
                const __half* W = g_proj_h + l * (128 * 128) + (sp * 4) * 128 + gp * 8;
                #pragma unroll
                for (int d = 0; d < 4; d++) wp[d] = *(const uint4*)(W + d * 128);
            }

            // ----- softmax (3 barriers; disjoint wred regions) -----
            {
                const bool valid = (jj <= i);
                float mx = logit;
                #pragma unroll
                for (int o = 16; o > 0; o >>= 1)
                    mx = fmaxf(mx, __shfl_xor_sync(0xffffffffu, mx, o));
                if ((tid & 31) == 0) wred[tid >> 5] = mx;
                __syncthreads();
                float hmax = fmaxf(fmaxf(wred[hh * 4 + 0], wred[hh * 4 + 1]),
                                   fmaxf(wred[hh * 4 + 2], wred[hh * 4 + 3]));
                float p = valid ? expf(logit - hmax) : 0.f;
                float ssum = p;
                #pragma unroll
                for (int o = 16; o > 0; o >>= 1)
                    ssum += __shfl_xor_sync(0xffffffffu, ssum, o);
                if ((tid & 31) == 0) wred[16 + (tid >> 5)] = ssum;
                __syncthreads();
                float hsum = wred[16 + hh * 4 + 0] + wred[16 + hh * 4 + 1]
                           + wred[16 + hh * 4 + 2] + wred[16 + hh * 4 + 3];
                att[hh * 128 + jj] = p / hsum;
            }
            __syncthreads();

            // ----- o = att @ V (registers + vcur) -----
            {
                const float* ap = att + (dim >> 5) * 128;
                float a0=0.f, a1=0.f, a2=0.f, a3=0.f;
                #pragma unroll
                for (int t = 0; t < 32; t += 4) {
                    int j = j0 + t;
                    float v0 = (j + 0 == i) ? vcur[dim] : vv[t + 0];
                    float v1 = (j + 1 == i) ? vcur[dim] : vv[t + 1];
                    float v2 = (j + 2 == i) ? vcur[dim] : vv[t + 2];
                    float v3 = (j + 3 == i) ? vcur[dim] : vv[t + 3];
                    a0 += ap[j + 0] * v0;
                    a1 += ap[j + 1] * v1;
                    a2 += ap[j + 2] * v2;
                    a3 += ap[j + 3] * v3;
                }
                red[s4 * 128 + dim] = (a0 + a1) + (a2 + a3);
            }
            __syncthreads();
            if (tid < 128)
                ob[tid] = red[tid] + red[128 + tid] + red[256 + tid] + red[384 + tid];
            __syncthreads();

            // ----- proj FMA (prefetched wp) -----
            {
                const int sp = tid >> 4, gp = tid & 15;
                const float* op = ob + sp * 4;
                float a0=0,a1=0,a2=0,a3=0,a4=0,a5=0,a6=0,a7=0;
                #pragma unroll
                for (int d = 0; d < 4; d++) {
                    float o = op[d];
                    const __half2* h2 = reinterpret_cast<const __half2*>(&wp[d]);
                    float2 f0 = __half22float2(h2[0]);
                    float2 f1 = __half22float2(h2[1]);
                    float2 f2 = __half22float2(h2[2]);
                    float2 f3 = __half22float2(h2[3]);
                    a0 += o*f0.x; a1 += o*f0.y; a2 += o*f1.x; a3 += o*f1.y;
                    a4 += o*f2.x; a5 += o*f2.y; a6 += o*f3.x; a7 += o*f3.y;
                }
                float4* rp = (float4*)(red + sp * 128 + gp * 8);
                rp[0] = make_float4(a0, a1, a2, a3);
                rp[1] = make_float4(a4, a5, a6, a7);
            }

            // === prefetch fc weights (hidden behind proj reduce + ln2) ===
            uint4 wf[16];
            const int sf = tid >> 6, gf = tid & 63;
            {
                const __half* W = g_fc_h + l * (128 * 512) + (sf * 16) * 512 + gf * 8;
                #pragma unroll
                for (int d = 0; d < 16; d++) wf[d] = *(const uint4*)(W + d * 512);
            }
            __syncthreads();
            if (tid < 128) {
                float acc = projb_s[l * 128 + tid];
                #pragma unroll
                for (int s = 0; s < 32; s++) acc += red[s * 128 + tid];
                xb[tid] += acc;
            }
            __syncthreads();

            // ----- ln2 -----
            block_layernorm(xb, hb, ln2w_s + l * 128, ln2b_s + l * 128, wred, tid);

            // ----- fc FMA (prefetched wf) -----
            {
                const float* hp = hb + sf * 16;
                float a0=0,a1=0,a2=0,a3=0,a4=0,a5=0,a6=0,a7=0;
                #pragma unroll
                for (int d = 0; d < 16; d++) {
                    float h = hp[d];
                    const __half2* h2 = reinterpret_cast<const __half2*>(&wf[d]);
                    float2 f0 = __half22float2(h2[0]);
                    float2 f1 = __half22float2(h2[1]);
                    float2 f2 = __half22float2(h2[2]);
                    float2 f3 = __half22float2(h2[3]);
                    a0 += h*f0.x; a1 += h*f0.y; a2 += h*f1.x; a3 += h*f1.y;
                    a4 += h*f2.x; a5 += h*f2.y; a6 += h*f3.x; a7 += h*f3.y;
                }
                float4* rp = (float4*)(red + sf * 512 + gf * 8);
                rp[0] = make_float4(a0, a1, a2, a3);
                rp[1] = make_float4(a4, a5, a6, a7);
            }

            // === prefetch fc2 weights (hidden behind fc reduce + gelu) ===
            uint4 wf2[16];
            const int s2 = tid >> 4, g2 = tid & 15;
            {
                const __half* W = g_fc2_h + l * (512 * 128) + (s2 * 16) * 128 + g2 * 8;
                #pragma unroll
                for (int d = 0; d < 16; d++) wf2[d] = *(const uint4*)(W + d * 128);
            }
            __syncthreads();
            {
                float t = fcb_s[l * 512 + tid];
                #pragma unroll
                for (int s = 0; s < 8; s++) t += red[s * 512 + tid];
                float inner = 0.7978845608028654f * (t + 0.044715f * t * t * t);
                gb[tid] = 0.5f * t * (1.f + tanhf(inner));
            }
            __syncthreads();

            // ----- fc2 FMA (prefetched wf2) -----
            {
                const float* gp = gb + s2 * 16;
                float a0=0,a1=0,a2=0,a3=0,a4=0,a5=0,a6=0,a7=0;
                #pragma unroll
                for (int d = 0; d < 16; d++) {
                    float gv = gp[d];
                    const __half2* h2 = reinterpret_cast<const __half2*>(&wf2[d]);
                    float2 f0 = __half22float2(h2[0]);
                    float2 f1 = __half22float2(h2[1]);
                    float2 f2 = __half22float2(h2[2]);
                    float2 f3 = __half22float2(h2[3]);
                    a0 += gv*f0.x; a1 += gv*f0.y; a2 += gv*f1.x; a3 += gv*f1.y;
                    a4 += gv*f2.x; a5 += gv*f2.y; a6 += gv*f3.x; a7 += gv*f3.y;
                }
                float4* rp = (float4*)(red + s2 * 128 + g2 * 8);
                rp[0] = make_float4(a0, a1, a2, a3);
                rp[1] = make_float4(a4, a5, a6, a7);
            }
            __syncthreads();
            if (tid < 128) {
                float acc = fc2b_s[l * 128 + tid];
                #pragma unroll
                for (int s = 0; s < 32; s++) acc += red[s * 128 + tid];
                xb[tid] += acc;
            }
            __syncthreads();
        } // layers

        // ----- final LN + head -> u_next; state update -----
        block_layernorm(xb, hb, lnfw_s, lnfb_s, wred, tid);
        {
            float part = (tid < 128) ? hb[tid] * headw_s[tid] : 0.f;
            #pragma unroll
            for (int o = 16; o > 0; o >>= 1)
                part += __shfl_xor_sync(0xffffffffu, part, o);
            if ((tid & 31) == 0) wred[tid >> 5] = part;
            __syncthreads();
            if (tid == 0) {
                float u = wred[0] + wred[1] + wred[2] + wred[3] + scal[2];
                float sn = s_cur + (-p0 * s_cur + p1 * tanhf(u));
                scal[0] = sn;   // s_{i+1}
                scal[1] = u;    // U[:, i+1]
            }
            __syncthreads();
        }
    } // steps
}

extern "C" void kernel_launch(void* const* d_in, const int* in_sizes, int n_in,
                              void* d_out, int out_size)
{
    (void)in_sizes; (void)n_in; (void)out_size;

    cvt_qkv <<<(NLAYER*128*384 + 1023)/1024, 1024>>>((const float*)d_in[9]);
    cvt_proj<<<(NLAYER*128*128 + 1023)/1024, 1024>>>((const float*)d_in[11]);
    cvt_fc  <<<(NLAYER*128*512 + 1023)/1024, 1024>>>((const float*)d_in[13]);
    cvt_fc2 <<<(NLAYER*512*128 + 1023)/1024, 1024>>>((const float*)d_in[15]);

    const size_t smem_bytes = (size_t)SMEM_FLOATS * sizeof(float);
    cudaFuncSetAttribute(gpt_rollout_kernel,
                         cudaFuncAttributeMaxDynamicSharedMemorySize,
                         (int)smem_bytes);
    gpt_rollout_kernel<<<BATCH, NTHREADS, smem_bytes>>>(
        (const float*)d_in[0],   // data
        (const float*)d_in[1],   // r
        (const float*)d_in[2],   // wte_w
        (const float*)d_in[3],   // wte_b
        (const float*)d_in[4],   // wpe
        (const float*)d_in[5],   // ln1_w
        (const float*)d_in[6],   // ln1_b
        (const float*)d_in[7],   // ln2_w
        (const float*)d_in[8],   // ln2_b
        (const float*)d_in[10],  // qkv_b
        (const float*)d_in[12],  // attn_proj_b
        (const float*)d_in[14],  // fc_b
        (const float*)d_in[16],  // fc2_b
        (const float*)d_in[17],  // lnf_w
        (const float*)d_in[18],  // lnf_b
        (const float*)d_in[19],  // head_w
        (const float*)d_in[20],  // head_b
        (float*)d_out);
}

// round 12
// speedup vs baseline: 1.1620x; 1.1620x over previous
#include <cuda_runtime.h>
#include <cuda_fp16.h>
#include <math.h>

// GPTClosedLoop: 128-step closed-loop rollout of a tiny GPT.
// B=32, T_H=128, NR=1, L=6, D=128, H=4, DH=32.
//
// KV-cache incremental decode, one CTA per batch. fp16 weight staging.
// Round 9: R7 base + SMEM param preload + weight-only register prefetch
// (one buffer live at a time; no KV register prefetch -> no spills),
// 3-barrier softmax, fixed-trip AV loop.

#define BATCH    32
#define TH       128
#define DMODEL   128
#define NLAYER   6
#define NHEAD    4
#define DH       32
#define NTHREADS 512

// KV cache: K [b][l][dim][token], V [b][l][token][dim]
__device__ float g_k[BATCH * NLAYER * DMODEL * TH];
__device__ float g_v[BATCH * NLAYER * TH * DMODEL];

// fp16 weight stages
__device__ __half g_qkv_h [NLAYER * 128 * 384];
__device__ __half g_proj_h[NLAYER * 128 * 128];
__device__ __half g_fc_h  [NLAYER * 128 * 512];
__device__ __half g_fc2_h [NLAYER * 512 * 128];

__global__ void cvt_qkv (const float* __restrict__ s){ int i = blockIdx.x*1024+threadIdx.x; if (i < NLAYER*128*384) g_qkv_h [i] = __float2half_rn(s[i]); }
__global__ void cvt_proj(const float* __restrict__ s){ int i = blockIdx.x*1024+threadIdx.x; if (i < NLAYER*128*128) g_proj_h[i] = __float2half_rn(s[i]); }
__global__ void cvt_fc  (const float* __restrict__ s){ int i = blockIdx.x*1024+threadIdx.x; if (i < NLAYER*128*512) g_fc_h  [i] = __float2half_rn(s[i]); }
__global__ void cvt_fc2 (const float* __restrict__ s){ int i = blockIdx.x*1024+threadIdx.x; if (i < NLAYER*512*128) g_fc2_h [i] = __float2half_rn(s[i]); }

// SMEM layout (floats)
#define OFF_WPE   0                    // 128*128
#define OFF_QKVB  (OFF_WPE  + 16384)   // 6*384
#define OFF_FCB   (OFF_QKVB + 2304)    // 6*512
#define OFF_PROJB (OFF_FCB  + 3072)    // 6*128
#define OFF_FC2B  (OFF_PROJB+ 768)     // 6*128
#define OFF_LN1W  (OFF_FC2B + 768)     // 6*128
#define OFF_LN1B  (OFF_LN1W + 768)
#define OFF_LN2W  (OFF_LN1B + 768)
#define OFF_LN2B  (OFF_LN2W + 768)
#define OFF_LNFW  (OFF_LN2B + 768)     // 128
#define OFF_LNFB  (OFF_LNFW + 128)
#define OFF_HEADW (OFF_LNFB + 128)
#define OFF_WTEW  (OFF_HEADW+ 128)     // 256
#define OFF_WTEB  (OFF_WTEW + 256)     // 128
#define OFF_RS    (OFF_WTEB + 128)     // 128
#define OFF_XB    (OFF_RS   + 128)
#define OFF_HB    (OFF_XB   + 128)
#define OFF_QB    (OFF_HB   + 128)
#define OFF_OB    (OFF_QB   + 128)
#define OFF_ATT   (OFF_OB   + 128)     // 512
#define OFF_GB    (OFF_ATT  + 512)     // 512
#define OFF_RED   (OFF_GB   + 512)     // 4096
#define OFF_WRED  (OFF_RED  + 4096)    // 32
#define OFF_SCAL  (OFF_WRED + 32)      // 4
#define SMEM_FLOATS (OFF_SCAL + 4)

__device__ __forceinline__ void block_layernorm(
    const float* __restrict__ in, float* __restrict__ outb,
    const float* __restrict__ w, const float* __restrict__ b,
    float* wred, int tid)
{
    float v = (tid < 128) ? in[tid] : 0.f;
    float s1 = v, s2 = v * v;
    #pragma unroll
    for (int o = 16; o > 0; o >>= 1) {
        s1 += __shfl_xor_sync(0xffffffffu, s1, o);
        s2 += __shfl_xor_sync(0xffffffffu, s2, o);
    }
    if ((tid & 31) == 0) { wred[tid >> 5] = s1; wred[16 + (tid >> 5)] = s2; }
    __syncthreads();
    float m   = (wred[0] + wred[1] + wred[2] + wred[3]) * (1.f / 128.f);
    float ex2 = (wred[16] + wred[17] + wred[18] + wred[19]) * (1.f / 128.f);
    float rstd = rsqrtf(ex2 - m * m + 1e-5f);
    if (tid < 128) outb[tid] = (v - m) * rstd * w[tid] + b[tid];
    __syncthreads();
}

__global__ __launch_bounds__(NTHREADS, 1)
void gpt_rollout_kernel(
    const float* __restrict__ data,
    const float* __restrict__ r,
    const float* __restrict__ wte_w,  const float* __restrict__ wte_b,
    const float* __restrict__ wpe,
    const float* __restrict__ ln1_w,  const float* __restrict__ ln1_b,
    const float* __restrict__ ln2_w,  const float* __restrict__ ln2_b,
    const float* __restrict__ qkv_b,
    const float* __restrict__ proj_b,
    const float* __restrict__ fc_b,
    const float* __restrict__ fc2_b,
    const float* __restrict__ lnf_w,  const float* __restrict__ lnf_b,
    const float* __restrict__ head_w, const float* __restrict__ head_b,
    float* __restrict__ out)
{
    extern __shared__ float sm[];
    float* wpe_s   = sm + OFF_WPE;
    float* qkvb_s  = sm + OFF_QKVB;
    float* fcb_s   = sm + OFF_FCB;
    float* projb_s = sm + OFF_PROJB;
    float* fc2b_s  = sm + OFF_FC2B;
    float* ln1w_s  = sm + OFF_LN1W;
    float* ln1b_s  = sm + OFF_LN1B;
    float* ln2w_s  = sm + OFF_LN2W;
    float* ln2b_s  = sm + OFF_LN2B;
    float* lnfw_s  = sm + OFF_LNFW;
    float* lnfb_s  = sm + OFF_LNFB;
    float* headw_s = sm + OFF_HEADW;
    float* wtew_s  = sm + OFF_WTEW;
    float* wteb_s  = sm + OFF_WTEB;
    float* rs      = sm + OFF_RS;
    float* xb      = sm + OFF_XB;
    float* hb      = sm + OFF_HB;
    float* qb      = sm + OFF_QB;
    float* ob      = sm + OFF_OB;
    float* att     = sm + OFF_ATT;
    float* gb      = sm + OFF_GB;
    float* red     = sm + OFF_RED;
    float* wred    = sm + OFF_WRED;
    float* scal    = sm + OFF_SCAL;

    const int b   = blockIdx.x;
    const int tid = threadIdx.x;

    const float p0 = data[b * 2 + 0];
    const float p1 = data[b * 2 + 1];

    // ----- one-time preload of all small params into SMEM -----
    for (int idx = tid; idx < 16384; idx += NTHREADS) wpe_s[idx]  = wpe[idx];
    for (int idx = tid; idx < 2304;  idx += NTHREADS) qkvb_s[idx] = qkv_b[idx];
    for (int idx = tid; idx < 3072;  idx += NTHREADS) fcb_s[idx]  = fc_b[idx];
    for (int idx = tid; idx < 768;   idx += NTHREADS) {
        projb_s[idx] = proj_b[idx];
        fc2b_s[idx]  = fc2_b[idx];
        ln1w_s[idx]  = ln1_w[idx];
        ln1b_s[idx]  = ln1_b[idx];
        ln2w_s[idx]  = ln2_w[idx];
        ln2b_s[idx]  = ln2_b[idx];
    }
    if (tid < 128) {
        lnfw_s[tid]  = lnf_w[tid];
        lnfb_s[tid]  = lnf_b[tid];
        headw_s[tid] = head_w[tid];
        wteb_s[tid]  = wte_b[tid];
        rs[tid]      = r[b * TH + tid];
    }
    if (tid < 256) wtew_s[tid] = wte_w[tid];
    if (tid == 0) { scal[0] = 0.f; scal[1] = 0.f; scal[2] = head_b[0]; }
    __syncthreads();

    for (int i = 0; i < TH; i++) {
        const float s_cur  = scal[0];
        const float u_prev = scal[1];
        if (tid == 0) out[b * TH + i] = s_cur;
        const float e = rs[i] - s_cur;

        if (tid < 128) {
            xb[tid] = e * wtew_s[tid] + u_prev * wtew_s[128 + tid]
                      + wteb_s[tid] + wpe_s[i * 128 + tid];
        }
        __syncthreads();

        for (int l = 0; l < NLAYER; l++) {
            float* kbase = g_k + (size_t)(b * NLAYER + l) * DMODEL * TH;
            float* vbase = g_v + (size_t)(b * NLAYER + l) * TH * DMODEL;

            // === prefetch qkv weights (hidden behind ln1; only live buffer) ===
            uint4 wq[16];
            const int sq = tid / 48, gq = tid % 48;
            if (tid < 384) {
                const __half* W = g_qkv_h + l * (128 * 384) + (sq * 16) * 384 + gq * 8;
                #pragma unroll
                for (int d = 0; d < 16; d++) wq[d] = *(const uint4*)(W + d * 384);
            }

            // ----- ln1 -----
            block_layernorm(xb, hb, ln1w_s + l * 128, ln1b_s + l * 128, wred, tid);

            // ----- qkv FMA: 8 K-segs(16) x 48 col-groups(x8) -----
            if (tid < 384) {
                const float* hp = hb + sq * 16;
                float a0=0,a1=0,a2=0,a3=0,a4=0,a5=0,a6=0,a7=0;
                #pragma unroll
                for (int d = 0; d < 16; d++) {
                    float h = hp[d];
                    const __half2* h2 = reinterpret_cast<const __half2*>(&wq[d]);
                    float2 f0 = __half22float2(h2[0]);
                    float2 f1 = __half22float2(h2[1]);
                    float2 f2 = __half22float2(h2[2]);
                    float2 f3 = __half22float2(h2[3]);
                    a0 += h*f0.x; a1 += h*f0.y; a2 += h*f1.x; a3 += h*f1.y;
                    a4 += h*f2.x; a5 += h*f2.y; a6 += h*f3.x; a7 += h*f3.y;
                }
                float4* rp = (float4*)(red + sq * 384 + gq * 8);
                rp[0] = make_float4(a0, a1, a2, a3);
                rp[1] = make_float4(a4, a5, a6, a7);
            }
            __syncthreads();

            // ----- qkv reduce -> q (SMEM) / K,V (global) -----
            if (tid < 384) {
                float acc = qkvb_s[l * 384 + tid];
                #pragma unroll
                for (int s = 0; s < 8; s++) acc += red[s * 384 + tid];
                if (tid < 128)      qb[tid] = acc;
                else if (tid < 256) kbase[(tid - 128) * TH + i] = acc;
                else                vbase[i * DMODEL + (tid - 256)] = acc;
            }
            __syncthreads();   // K/V writes visible block-wide

            // ----- attention logits (thread = (head, key j)) -----
            const int hh = tid >> 7;
            const int jj = tid & 127;
            float logit;
            {
                const bool valid = (jj <= i);
                const float* kp = kbase + (hh * DH) * TH + jj;
                float dot = 0.f;
                #pragma unroll
                for (int d = 0; d < DH; d += 4) {
                    float4 qv = *(const float4*)(qb + hh * DH + d);
                    dot += qv.x * kp[(d + 0) * TH] + qv.y * kp[(d + 1) * TH]
                         + qv.z * kp[(d + 2) * TH] + qv.w * kp[(d + 3) * TH];
                }
                logit = valid ? dot * 0.17677669529663689f : -3.0e38f;
            }

            // === prefetch proj weights (hidden behind softmax) ===
            uint4 wp[4];
            {
                const int sp = tid >> 4, gp = tid & 15;
                const __half* W = g_proj_h + l * (128 * 128) + (sp * 4) * 128 + gp * 8;
                #pragma unroll
                for (int d = 0; d < 4; d++) wp[d] = *(const uint4*)(W + d * 128);
            }

            // ----- softmax (3 barriers; disjoint wred regions) -----
            {
                const bool valid = (jj <= i);
                float mx = logit;
                #pragma unroll
                for (int o = 16; o > 0; o >>= 1)
                    mx = fmaxf(mx, __shfl_xor_sync(0xffffffffu, mx, o));
                if ((tid & 31) == 0) wred[tid >> 5] = mx;
                __syncthreads();
                float hmax = fmaxf(fmaxf(wred[hh * 4 + 0], wred[hh * 4 + 1]),
                                   fmaxf(wred[hh * 4 + 2], wred[hh * 4 + 3]));
                float p = valid ? expf(logit - hmax) : 0.f;
                float ssum = p;
                #pragma unroll
                for (int o = 16; o > 0; o >>= 1)
                    ssum += __shfl_xor_sync(0xffffffffu, ssum, o);
                if ((tid & 31) == 0) wred[16 + (tid >> 5)] = ssum;
                __syncthreads();
                float hsum = wred[16 + hh * 4 + 0] + wred[16 + hh * 4 + 1]
                           + wred[16 + hh * 4 + 2] + wred[16 + hh * 4 + 3];
                att[hh * 128 + jj] = p / hsum;
            }
            __syncthreads();

            // ----- o = att @ V : fixed 32-trip j-split x4 (padding adds exact 0) -----
            {
                const int s4 = tid >> 7, dim = tid & 127;
                const int j0 = s4 * 32;
                const float* vp = vbase + dim;
                const float* ap = att + (dim >> 5) * 128;
                float a0=0.f, a1=0.f, a2=0.f, a3=0.f;
                #pragma unroll
                for (int t = 0; t < 32; t += 4) {
                    int j = j0 + t;
                    a0 += ap[j + 0] * vp[(j + 0) * DMODEL];
                    a1 += ap[j + 1] * vp[(j + 1) * DMODEL];
                    a2 += ap[j + 2] * vp[(j + 2) * DMODEL];
                    a3 += ap[j + 3] * vp[(j + 3) * DMODEL];
                }
                red[s4 * 128 + dim] = (a0 + a1) + (a2 + a3);
            }
            __syncthreads();
            if (tid < 128)
                ob[tid] = red[tid] + red[128 + tid] + red[256 + tid] + red[384 + tid];
            __syncthreads();

            // ----- proj FMA (prefetched wp) -----
            {
                const int sp = tid >> 4, gp = tid & 15;
                const float* op = ob + sp * 4;
                float a0=0,a1=0,a2=0,a3=0,a4=0,a5=0,a6=0,a7=0;
                #pragma unroll
                for (int d = 0; d < 4; d++) {
                    float o = op[d];
                    const __half2* h2 = reinterpret_cast<const __half2*>(&wp[d]);
                    float2 f0 = __half22float2(h2[0]);
                    float2 f1 = __half22float2(h2[1]);
                    float2 f2 = __half22float2(h2[2]);
                    float2 f3 = __half22float2(h2[3]);
                    a0 += o*f0.x; a1 += o*f0.y; a2 += o*f1.x; a3 += o*f1.y;
                    a4 += o*f2.x; a5 += o*f2.y; a6 += o*f3.x; a7 += o*f3.y;
                }
                float4* rp = (float4*)(red + sp * 128 + gp * 8);
                rp[0] = make_float4(a0, a1, a2, a3);
                rp[1] = make_float4(a4, a5, a6, a7);
            }

            // === prefetch fc weights (hidden behind proj reduce + ln2) ===
            uint4 wf[16];
            const int sf = tid >> 6, gf = tid & 63;
            {
                const __half* W = g_fc_h + l * (128 * 512) + (sf * 16) * 512 + gf * 8;
                #pragma unroll
                for (int d = 0; d < 16; d++) wf[d] = *(const uint4*)(W + d * 512);
            }
            __syncthreads();
            if (tid < 128) {
                float acc = projb_s[l * 128 + tid];
                #pragma unroll
                for (int s = 0; s < 32; s++) acc += red[s * 128 + tid];
                xb[tid] += acc;
            }
            __syncthreads();

            // ----- ln2 -----
            block_layernorm(xb, hb, ln2w_s + l * 128, ln2b_s + l * 128, wred, tid);

            // ----- fc FMA (prefetched wf) -----
            {
                const float* hp = hb + sf * 16;
                float a0=0,a1=0,a2=0,a3=0,a4=0,a5=0,a6=0,a7=0;
                #pragma unroll
                for (int d = 0; d < 16; d++) {
                    float h = hp[d];
                    const __half2* h2 = reinterpret_cast<const __half2*>(&wf[d]);
                    float2 f0 = __half22float2(h2[0]);
                    float2 f1 = __half22float2(h2[1]);
                    float2 f2 = __half22float2(h2[2]);
                    float2 f3 = __half22float2(h2[3]);
                    a0 += h*f0.x; a1 += h*f0.y; a2 += h*f1.x; a3 += h*f1.y;
                    a4 += h*f2.x; a5 += h*f2.y; a6 += h*f3.x; a7 += h*f3.y;
                }
                float4* rp = (float4*)(red + sf * 512 + gf * 8);
                rp[0] = make_float4(a0, a1, a2, a3);
                rp[1] = make_float4(a4, a5, a6, a7);
            }

            // === prefetch fc2 weights (hidden behind fc reduce + gelu) ===
            uint4 wf2[16];
            const int s2 = tid >> 4, g2 = tid & 15;
            {
                const __half* W = g_fc2_h + l * (512 * 128) + (s2 * 16) * 128 + g2 * 8;
                #pragma unroll
                for (int d = 0; d < 16; d++) wf2[d] = *(const uint4*)(W + d * 128);
            }
            __syncthreads();
            {
                float t = fcb_s[l * 512 + tid];
                #pragma unroll
                for (int s = 0; s < 8; s++) t += red[s * 512 + tid];
                float inner = 0.7978845608028654f * (t + 0.044715f * t * t * t);
                gb[tid] = 0.5f * t * (1.f + tanhf(inner));
            }
            __syncthreads();

            // ----- fc2 FMA (prefetched wf2) -----
            {
                const float* gp = gb + s2 * 16;
                float a0=0,a1=0,a2=0,a3=0,a4=0,a5=0,a6=0,a7=0;
                #pragma unroll
                for (int d = 0; d < 16; d++) {
                    float gv = gp[d];
                    const __half2* h2 = reinterpret_cast<const __half2*>(&wf2[d]);
                    float2 f0 = __half22float2(h2[0]);
                    float2 f1 = __half22float2(h2[1]);
                    float2 f2 = __half22float2(h2[2]);
                    float2 f3 = __half22float2(h2[3]);
                    a0 += gv*f0.x; a1 += gv*f0.y; a2 += gv*f1.x; a3 += gv*f1.y;
                    a4 += gv*f2.x; a5 += gv*f2.y; a6 += gv*f3.x; a7 += gv*f3.y;
                }
                float4* rp = (float4*)(red + s2 * 128 + g2 * 8);
                rp[0] = make_float4(a0, a1, a2, a3);
                rp[1] = make_float4(a4, a5, a6, a7);
            }
            __syncthreads();
            if (tid < 128) {
                float acc = fc2b_s[l * 128 + tid];
                #pragma unroll
                for (int s = 0; s < 32; s++) acc += red[s * 128 + tid];
                xb[tid] += acc;
            }
            __syncthreads();
        } // layers

        // ----- final LN + head -> u_next; state update -----
        block_layernorm(xb, hb, lnfw_s, lnfb_s, wred, tid);
        {
            float part = (tid < 128) ? hb[tid] * headw_s[tid] : 0.f;
            #pragma unroll
            for (int o = 16; o > 0; o >>= 1)
                part += __shfl_xor_sync(0xffffffffu, part, o);
            if ((tid & 31) == 0) wred[tid >> 5] = part;
            __syncthreads();
            if (tid == 0) {
                float u = wred[0] + wred[1] + wred[2] + wred[3] + scal[2];
                float sn = s_cur + (-p0 * s_cur + p1 * tanhf(u));
                scal[0] = sn;   // s_{i+1}
                scal[1] = u;    // U[:, i+1]
            }
            __syncthreads();
        }
    } // steps
}

extern "C" void kernel_launch(void* const* d_in, const int* in_sizes, int n_in,
                              void* d_out, int out_size)
{
    (void)in_sizes; (void)n_in; (void)out_size;

    cvt_qkv <<<(NLAYER*128*384 + 1023)/1024, 1024>>>((const float*)d_in[9]);
    cvt_proj<<<(NLAYER*128*128 + 1023)/1024, 1024>>>((const float*)d_in[11]);
    cvt_fc  <<<(NLAYER*128*512 + 1023)/1024, 1024>>>((const float*)d_in[13]);
    cvt_fc2 <<<(NLAYER*512*128 + 1023)/1024, 1024>>>((const float*)d_in[15]);

    const size_t smem_bytes = (size_t)SMEM_FLOATS * sizeof(float);
    cudaFuncSetAttribute(gpt_rollout_kernel,
                         cudaFuncAttributeMaxDynamicSharedMemorySize,
                         (int)smem_bytes);
    gpt_rollout_kernel<<<BATCH, NTHREADS, smem_bytes>>>(
        (const float*)d_in[0],   // data
        (const float*)d_in[1],   // r
        (const float*)d_in[2],   // wte_w
        (const float*)d_in[3],   // wte_b
        (const float*)d_in[4],   // wpe
        (const float*)d_in[5],   // ln1_w
        (const float*)d_in[6],   // ln1_b
        (const float*)d_in[7],   // ln2_w
        (const float*)d_in[8],   // ln2_b
        (const float*)d_in[10],  // qkv_b
        (const float*)d_in[12],  // attn_proj_b
        (const float*)d_in[14],  // fc_b
        (const float*)d_in[16],  // fc2_b
        (const float*)d_in[17],  // lnf_w
        (const float*)d_in[18],  // lnf_b
        (const float*)d_in[19],  // head_w
        (const float*)d_in[20],  // head_b
        (float*)d_out);
}

// round 14
// speedup vs baseline: 1.3132x; 1.1301x over previous
#include <cuda_runtime.h>
#include <cuda_fp16.h>
#include <math.h>

// GPTClosedLoop: 128-step closed-loop rollout of a tiny GPT.
// B=32, T_H=128, NR=1, L=6, D=128, H=4, DH=32.
//
// KV-cache incremental decode, one CTA per batch. fp16 weight staging.
// Round 12: R7 base (NO register prefetch -> no spills) + SMEM param preload
// + kcur stash + predicated KV loads + 3-barrier softmax + merged cvt kernel.

#define BATCH    32
#define TH       128
#define DMODEL   128
#define NLAYER   6
#define NHEAD    4
#define DH       32
#define NTHREADS 512

// KV cache: K [b][l][dim][token], V [b][l][token][dim]
__device__ float g_k[BATCH * NLAYER * DMODEL * TH];
__device__ float g_v[BATCH * NLAYER * TH * DMODEL];

// fp16 weight stages
__device__ __half g_qkv_h [NLAYER * 128 * 384];
__device__ __half g_proj_h[NLAYER * 128 * 128];
__device__ __half g_fc_h  [NLAYER * 128 * 512];
__device__ __half g_fc2_h [NLAYER * 512 * 128];

__global__ void cvt_all(const float* __restrict__ qkv, const float* __restrict__ proj,
                        const float* __restrict__ fc,  const float* __restrict__ fc2)
{
    int i = blockIdx.x * 1024 + threadIdx.x;
    if (i < NLAYER*128*384) g_qkv_h [i] = __float2half_rn(qkv[i]);
    if (i < NLAYER*128*128) g_proj_h[i] = __float2half_rn(proj[i]);
    if (i < NLAYER*128*512) g_fc_h  [i] = __float2half_rn(fc[i]);
    if (i < NLAYER*512*128) g_fc2_h [i] = __float2half_rn(fc2[i]);
}

// SMEM layout (floats)
#define OFF_WPE   0                    // 128*128
#define OFF_QKVB  (OFF_WPE  + 16384)   // 6*384
#define OFF_FCB   (OFF_QKVB + 2304)    // 6*512
#define OFF_PROJB (OFF_FCB  + 3072)    // 6*128
#define OFF_FC2B  (OFF_PROJB+ 768)
#define OFF_LN1W  (OFF_FC2B + 768)
#define OFF_LN1B  (OFF_LN1W + 768)
#define OFF_LN2W  (OFF_LN1B + 768)
#define OFF_LN2B  (OFF_LN2W + 768)
#define OFF_LNFW  (OFF_LN2B + 768)     // 128
#define OFF_LNFB  (OFF_LNFW + 128)
#define OFF_HEADW (OFF_LNFB + 128)
#define OFF_WTEW  (OFF_HEADW+ 128)     // 256
#define OFF_WTEB  (OFF_WTEW + 256)     // 128
#define OFF_RS    (OFF_WTEB + 128)     // 128
#define OFF_XB    (OFF_RS   + 128)
#define OFF_HB    (OFF_XB   + 128)
#define OFF_QB    (OFF_HB   + 128)
#define OFF_OB    (OFF_QB   + 128)
#define OFF_KCUR  (OFF_OB   + 128)
#define OFF_VCUR  (OFF_KCUR + 128)
#define OFF_ATT   (OFF_VCUR + 128)     // 512
#define OFF_GB    (OFF_ATT  + 512)     // 512
#define OFF_RED   (OFF_GB   + 512)     // 4096
#define OFF_WRED  (OFF_RED  + 4096)    // 32
#define OFF_SCAL  (OFF_WRED + 32)      // 4
#define SMEM_FLOATS (OFF_SCAL + 4)

__device__ __forceinline__ void block_layernorm(
    const float* __restrict__ in, float* __restrict__ outb,
    const float* __restrict__ w, const float* __restrict__ b,
    float* wred, int tid)
{
    float v = (tid < 128) ? in[tid] : 0.f;
    float s1 = v, s2 = v * v;
    #pragma unroll
    for (int o = 16; o > 0; o >>= 1) {
        s1 += __shfl_xor_sync(0xffffffffu, s1, o);
        s2 += __shfl_xor_sync(0xffffffffu, s2, o);
    }
    if ((tid & 31) == 0) { wred[tid >> 5] = s1; wred[16 + (tid >> 5)] = s2; }
    __syncthreads();
    float m   = (wred[0] + wred[1] + wred[2] + wred[3]) * (1.f / 128.f);
    float ex2 = (wred[16] + wred[17] + wred[18] + wred[19]) * (1.f / 128.f);
    float rstd = rsqrtf(ex2 - m * m + 1e-5f);
    if (tid < 128) outb[tid] = (v - m) * rstd * w[tid] + b[tid];
    __syncthreads();
}

__global__ __launch_bounds__(NTHREADS, 1)
void gpt_rollout_kernel(
    const float* __restrict__ data,
    const float* __restrict__ r,
    const float* __restrict__ wte_w,  const float* __restrict__ wte_b,
    const float* __restrict__ wpe,
    const float* __restrict__ ln1_w,  const float* __restrict__ ln1_b,
    const float* __restrict__ ln2_w,  const float* __restrict__ ln2_b,
    const float* __restrict__ qkv_b,
    const float* __restrict__ proj_b,
    const float* __restrict__ fc_b,
    const float* __restrict__ fc2_b,
    const float* __restrict__ lnf_w,  const float* __restrict__ lnf_b,
    const float* __restrict__ head_w, const float* __restrict__ head_b,
    float* __restrict__ out)
{
    extern __shared__ float sm[];
    float* wpe_s   = sm + OFF_WPE;
    float* qkvb_s  = sm + OFF_QKVB;
    float* fcb_s   = sm + OFF_FCB;
    float* projb_s = sm + OFF_PROJB;
    float* fc2b_s  = sm + OFF_FC2B;
    float* ln1w_s  = sm + OFF_LN1W;
    float* ln1b_s  = sm + OFF_LN1B;
    float* ln2w_s  = sm + OFF_LN2W;
    float* ln2b_s  = sm + OFF_LN2B;
    float* lnfw_s  = sm + OFF_LNFW;
    float* lnfb_s  = sm + OFF_LNFB;
    float* headw_s = sm + OFF_HEADW;
    float* wtew_s  = sm + OFF_WTEW;
    float* wteb_s  = sm + OFF_WTEB;
    float* rs      = sm + OFF_RS;
    float* xb      = sm + OFF_XB;
    float* hb      = sm + OFF_HB;
    float* qb      = sm + OFF_QB;
    float* ob      = sm + OFF_OB;
    float* kcur    = sm + OFF_KCUR;
    float* vcur    = sm + OFF_VCUR;
    float* att     = sm + OFF_ATT;
    float* gb      = sm + OFF_GB;
    float* red     = sm + OFF_RED;
    float* wred    = sm + OFF_WRED;
    float* scal    = sm + OFF_SCAL;

    const int b   = blockIdx.x;
    const int tid = threadIdx.x;

    const float p0 = data[b * 2 + 0];
    const float p1 = data[b * 2 + 1];

    // ----- one-time preload of all small params into SMEM -----
    for (int idx = tid; idx < 16384; idx += NTHREADS) wpe_s[idx]  = wpe[idx];
    for (int idx = tid; idx < 2304;  idx += NTHREADS) qkvb_s[idx] = qkv_b[idx];
    for (int idx = tid; idx < 3072;  idx += NTHREADS) fcb_s[idx]  = fc_b[idx];
    for (int idx = tid; idx < 768;   idx += NTHREADS) {
        projb_s[idx] = proj_b[idx];
        fc2b_s[idx]  = fc2_b[idx];
        ln1w_s[idx]  = ln1_w[idx];
        ln1b_s[idx]  = ln1_b[idx];
        ln2w_s[idx]  = ln2_w[idx];
        ln2b_s[idx]  = ln2_b[idx];
    }
    if (tid < 128) {
        lnfw_s[tid]  = lnf_w[tid];
        lnfb_s[tid]  = lnf_b[tid];
        headw_s[tid] = head_w[tid];
        wteb_s[tid]  = wte_b[tid];
        rs[tid]      = r[b * TH + tid];
    }
    if (tid < 256) wtew_s[tid] = wte_w[tid];
    if (tid == 0) { scal[0] = 0.f; scal[1] = 0.f; scal[2] = head_b[0]; }
    __syncthreads();

    for (int i = 0; i < TH; i++) {
        const float s_cur  = scal[0];
        const float u_prev = scal[1];
        if (tid == 0) out[b * TH + i] = s_cur;
        const float e = rs[i] - s_cur;

        if (tid < 128) {
            xb[tid] = e * wtew_s[tid] + u_prev * wtew_s[128 + tid]
                      + wteb_s[tid] + wpe_s[i * 128 + tid];
        }
        __syncthreads();

        for (int l = 0; l < NLAYER; l++) {
            float* kbase = g_k + (size_t)(b * NLAYER + l) * DMODEL * TH;
            float* vbase = g_v + (size_t)(b * NLAYER + l) * TH * DMODEL;

            // ----- ln1 -----
            block_layernorm(xb, hb, ln1w_s + l * 128, ln1b_s + l * 128, wred, tid);

            // ----- qkv: 48 col-groups(x8) * 8 K-segs(16) = 384 thr, 16 loads -----
            if (tid < 384) {
                const int sq = tid / 48, gq = tid % 48;
                const __half* W = g_qkv_h + l * (128 * 384) + (sq * 16) * 384 + gq * 8;
                const float* hp = hb + sq * 16;
                float a0=0,a1=0,a2=0,a3=0,a4=0,a5=0,a6=0,a7=0;
                #pragma unroll
                for (int d = 0; d < 16; d++) {
                    float h = hp[d];
                    uint4 wv = *(const uint4*)(W + d * 384);
                    const __half2* h2 = reinterpret_cast<const __half2*>(&wv);
                    float2 f0 = __half22float2(h2[0]);
                    float2 f1 = __half22float2(h2[1]);
                    float2 f2 = __half22float2(h2[2]);
                    float2 f3 = __half22float2(h2[3]);
                    a0 += h*f0.x; a1 += h*f0.y; a2 += h*f1.x; a3 += h*f1.y;
                    a4 += h*f2.x; a5 += h*f2.y; a6 += h*f3.x; a7 += h*f3.y;
                }
                float4* rp = (float4*)(red + sq * 384 + gq * 8);
                rp[0] = make_float4(a0, a1, a2, a3);
                rp[1] = make_float4(a4, a5, a6, a7);
            }
            __syncthreads();

            // ----- qkv reduce -> q (SMEM) / K,V (global + SMEM stash) -----
            if (tid < 384) {
                float acc = qkvb_s[l * 384 + tid];
                #pragma unroll
                for (int s = 0; s < 8; s++) acc += red[s * 384 + tid];
                if (tid < 128)      qb[tid] = acc;
                else if (tid < 256) { kbase[(tid - 128) * TH + i] = acc; kcur[tid - 128] = acc; }
                else                { vbase[i * DMODEL + (tid - 256)] = acc; vcur[tid - 256] = acc; }
            }
            __syncthreads();

            // ----- attention logits (thread = (head, key j)); j>i lanes skip loads -----
            const int hh = tid >> 7;
            const int jj = tid & 127;
            float logit = -3.0e38f;
            if (jj < i) {
                const float* kp = kbase + (hh * DH) * TH + jj;
                float dot = 0.f;
                #pragma unroll
                for (int d = 0; d < DH; d += 4) {
                    float4 qv = *(const float4*)(qb + hh * DH + d);
                    dot += qv.x * kp[(d + 0) * TH] + qv.y * kp[(d + 1) * TH]
                         + qv.z * kp[(d + 2) * TH] + qv.w * kp[(d + 3) * TH];
                }
                logit = dot * 0.17677669529663689f;
            } else if (jj == i) {
                const float* kp = kcur + hh * DH;
                float dot = 0.f;
                #pragma unroll
                for (int d = 0; d < DH; d += 4) {
                    float4 qv = *(const float4*)(qb + hh * DH + d);
                    dot += qv.x * kp[d + 0] + qv.y * kp[d + 1]
                         + qv.z * kp[d + 2] + qv.w * kp[d + 3];
                }
                logit = dot * 0.17677669529663689f;
            }

            // ----- softmax (3 barriers; disjoint wred regions) -----
            {
                float mx = logit;
                #pragma unroll
                for (int o = 16; o > 0; o >>= 1)
                    mx = fmaxf(mx, __shfl_xor_sync(0xffffffffu, mx, o));
                if ((tid & 31) == 0) wred[tid >> 5] = mx;
                __syncthreads();
                float hmax = fmaxf(fmaxf(wred[hh * 4 + 0], wred[hh * 4 + 1]),
                                   fmaxf(wred[hh * 4 + 2], wred[hh * 4 + 3]));
                float p = (jj <= i) ? expf(logit - hmax) : 0.f;
                float ssum = p;
                #pragma unroll
                for (int o = 16; o > 0; o >>= 1)
                    ssum += __shfl_xor_sync(0xffffffffu, ssum, o);
                if ((tid & 31) == 0) wred[16 + (tid >> 5)] = ssum;
                __syncthreads();
                float hsum = wred[16 + hh * 4 + 0] + wred[16 + hh * 4 + 1]
                           + wred[16 + hh * 4 + 2] + wred[16 + hh * 4 + 3];
                att[hh * 128 + jj] = p / hsum;
            }
            __syncthreads();

            // ----- o = att @ V : fixed 32-trip j-split x4, loads predicated to j<=i -----
            {
                const int s4 = tid >> 7, dim = tid & 127;
                const int j0 = s4 * 32;
                const float* vp = vbase + dim;
                const float* ap = att + (dim >> 5) * 128;
                float a0=0.f, a1=0.f, a2=0.f, a3=0.f;
                #pragma unroll
                for (int t = 0; t < 32; t += 4) {
                    int j = j0 + t;
                    float v0 = (j + 0 < i) ? vp[(j + 0) * DMODEL] : ((j + 0 == i) ? vcur[dim] : 0.f);
                    float v1 = (j + 1 < i) ? vp[(j + 1) * DMODEL] : ((j + 1 == i) ? vcur[dim] : 0.f);
                    float v2 = (j + 2 < i) ? vp[(j + 2) * DMODEL] : ((j + 2 == i) ? vcur[dim] : 0.f);
                    float v3 = (j + 3 < i) ? vp[(j + 3) * DMODEL] : ((j + 3 == i) ? vcur[dim] : 0.f);
                    a0 += ap[j + 0] * v0;
                    a1 += ap[j + 1] * v1;
                    a2 += ap[j + 2] * v2;
                    a3 += ap[j + 3] * v3;
                }
                red[s4 * 128 + dim] = (a0 + a1) + (a2 + a3);
            }
            __syncthreads();
            if (tid < 128)
                ob[tid] = red[tid] + red[128 + tid] + red[256 + tid] + red[384 + tid];
            __syncthreads();

            // ----- proj: 16 col-groups(x8) * 32 K-segs(4) = 512 thr, 4 loads -----
            {
                const int sp = tid >> 4, gp = tid & 15;
                const __half* W = g_proj_h + l * (128 * 128) + (sp * 4) * 128 + gp * 8;
                const float* op = ob + sp * 4;
                float a0=0,a1=0,a2=0,a3=0,a4=0,a5=0,a6=0,a7=0;
                #pragma unroll
                for (int d = 0; d < 4; d++) {
                    float o = op[d];
                    uint4 wv = *(const uint4*)(W + d * 128);
                    const __half2* h2 = reinterpret_cast<const __half2*>(&wv);
                    float2 f0 = __half22float2(h2[0]);
                    float2 f1 = __half22float2(h2[1]);
                    float2 f2 = __half22float2(h2[2]);
                    float2 f3 = __half22float2(h2[3]);
                    a0 += o*f0.x; a1 += o*f0.y; a2 += o*f1.x; a3 += o*f1.y;
                    a4 += o*f2.x; a5 += o*f2.y; a6 += o*f3.x; a7 += o*f3.y;
                }
                float4* rp = (float4*)(red + sp * 128 + gp * 8);
                rp[0] = make_float4(a0, a1, a2, a3);
                rp[1] = make_float4(a4, a5, a6, a7);
            }
            __syncthreads();
            if (tid < 128) {
                float acc = projb_s[l * 128 + tid];
                #pragma unroll
                for (int s = 0; s < 32; s++) acc += red[s * 128 + tid];
                xb[tid] += acc;
            }
            __syncthreads();

            // ----- ln2 -----
            block_layernorm(xb, hb, ln2w_s + l * 128, ln2b_s + l * 128, wred, tid);

            // ----- fc: 64 col-groups(x8) * 8 K-segs(16) = 512 thr, 16 loads -----
            {
                const int sf = tid >> 6, gf = tid & 63;
                const __half* W = g_fc_h + l * (128 * 512) + (sf * 16) * 512 + gf * 8;
                const float* hp = hb + sf * 16;
                float a0=0,a1=0,a2=0,a3=0,a4=0,a5=0,a6=0,a7=0;
                #pragma unroll
                for (int d = 0; d < 16; d++) {
                    float h = hp[d];
                    uint4 wv = *(const uint4*)(W + d * 512);
                    const __half2* h2 = reinterpret_cast<const __half2*>(&wv);
                    float2 f0 = __half22float2(h2[0]);
                    float2 f1 = __half22float2(h2[1]);
                    float2 f2 = __half22float2(h2[2]);
                    float2 f3 = __half22float2(h2[3]);
                    a0 += h*f0.x; a1 += h*f0.y; a2 += h*f1.x; a3 += h*f1.y;
                    a4 += h*f2.x; a5 += h*f2.y; a6 += h*f3.x; a7 += h*f3.y;
                }
                float4* rp = (float4*)(red + sf * 512 + gf * 8);
                rp[0] = make_float4(a0, a1, a2, a3);
                rp[1] = make_float4(a4, a5, a6, a7);
            }
            __syncthreads();
            {
                float t = fcb_s[l * 512 + tid];
                #pragma unroll
                for (int s = 0; s < 8; s++) t += red[s * 512 + tid];
                float inner = 0.7978845608028654f * (t + 0.044715f * t * t * t);
                gb[tid] = 0.5f * t * (1.f + tanhf(inner));
            }
            __syncthreads();

            // ----- fc2: 16 col-groups(x8) * 32 K-segs(16) = 512 thr, 16 loads -----
            {
                const int s2 = tid >> 4, g2 = tid & 15;
                const __half* W = g_fc2_h + l * (512 * 128) + (s2 * 16) * 128 + g2 * 8;
                const float* gp = gb + s2 * 16;
                float a0=0,a1=0,a2=0,a3=0,a4=0,a5=0,a6=0,a7=0;
                #pragma unroll
                for (int d = 0; d < 16; d++) {
                    float gv = gp[d];
                    uint4 wv = *(const uint4*)(W + d * 128);
                    const __half2* h2 = reinterpret_cast<const __half2*>(&wv);
                    float2 f0 = __half22float2(h2[0]);
                    float2 f1 = __half22float2(h2[1]);
                    float2 f2 = __half22float2(h2[2]);
                    float2 f3 = __half22float2(h2[3]);
                    a0 += gv*f0.x; a1 += gv*f0.y; a2 += gv*f1.x; a3 += gv*f1.y;
                    a4 += gv*f2.x; a5 += gv*f2.y; a6 += gv*f3.x; a7 += gv*f3.y;
                }
                float4* rp = (float4*)(red + s2 * 128 + g2 * 8);
                rp[0] = make_float4(a0, a1, a2, a3);
                rp[1] = make_float4(a4, a5, a6, a7);
            }
            __syncthreads();
            if (tid < 128) {
                float acc = fc2b_s[l * 128 + tid];
                #pragma unroll
                for (int s = 0; s < 32; s++) acc += red[s * 128 + tid];
                xb[tid] += acc;
            }
            __syncthreads();
        } // layers

        // ----- final LN + head -> u_next; state update -----
        block_layernorm(xb, hb, lnfw_s, lnfb_s, wred, tid);
        {
            float part = (tid < 128) ? hb[tid] * headw_s[tid] : 0.f;
            #pragma unroll
            for (int o = 16; o > 0; o >>= 1)
                part += __shfl_xor_sync(0xffffffffu, part, o);
            if ((tid & 31) == 0) wred[tid >> 5] = part;
            __syncthreads();
            if (tid == 0) {
                float u = wred[0] + wred[1] + wred[2] + wred[3] + scal[2];
                float sn = s_cur + (-p0 * s_cur + p1 * tanhf(u));
                scal[0] = sn;   // s_{i+1}
                scal[1] = u;    // U[:, i+1]
            }
            __syncthreads();
        }
    } // steps
}

extern "C" void kernel_launch(void* const* d_in, const int* in_sizes, int n_in,
                              void* d_out, int out_size)
{
    (void)in_sizes; (void)n_in; (void)out_size;

    cvt_all<<<(NLAYER*128*512 + 1023)/1024, 1024>>>(
        (const float*)d_in[9], (const float*)d_in[11],
        (const float*)d_in[13], (const float*)d_in[15]);

    const size_t smem_bytes = (size_t)SMEM_FLOATS * sizeof(float);
    cudaFuncSetAttribute(gpt_rollout_kernel,
                         cudaFuncAttributeMaxDynamicSharedMemorySize,
                         (int)smem_bytes);
    gpt_rollout_kernel<<<BATCH, NTHREADS, smem_bytes>>>(
        (const float*)d_in[0],   // data
        (const float*)d_in[1],   // r
        (const float*)d_in[2],   // wte_w
        (const float*)d_in[3],   // wte_b
        (const float*)d_in[4],   // wpe
        (const float*)d_in[5],   // ln1_w
        (const float*)d_in[6],   // ln1_b
        (const float*)d_in[7],   // ln2_w
        (const float*)d_in[8],   // ln2_b
        (const float*)d_in[10],  // qkv_b
        (const float*)d_in[12],  // attn_proj_b
        (const float*)d_in[14],  // fc_b
        (const float*)d_in[16],  // fc2_b
        (const float*)d_in[17],  // lnf_w
        (const float*)d_in[18],  // lnf_b
        (const float*)d_in[19],  // head_w
        (const float*)d_in[20],  // head_b
        (float*)d_out);
}

// round 16
// speedup vs baseline: 1.5241x; 1.1606x over previous
#include <cuda_runtime.h>
#include <cuda_fp16.h>
#include <math.h>

// GPTClosedLoop: 128-step closed-loop rollout of a tiny GPT.
// B=32, T_H=128, NR=1, L=6, D=128, H=4, DH=32.
//
// Round 14: 2-CTA CLUSTER per batch element (64 CTAs). Head-split attention
// (rank r owns heads 2r,2r+1 -> attention fully CTA-local), column-split
// qkv/fc, K-split proj/fc2 with one DSMEM partial exchange + cluster barrier
// each (2 cluster syncs per layer total). Residual stream kept bit-identical
// in both CTAs (commutative partial sums), so LN/head are redundant, not
// synchronized. fp16 weight staging as before.

#define BATCH    32
#define TH       128
#define DMODEL   128
#define NLAYER   6
#define NTHREADS 512

// KV cache: K [b][l][dim][token], V [b][l][token][dim]  (dims split across ranks)
__device__ float g_k[BATCH * NLAYER * DMODEL * TH];
__device__ float g_v[BATCH * NLAYER * TH * DMODEL];

// fp16 weight stages
__device__ __half g_qkv_h [NLAYER * 128 * 384];
__device__ __half g_proj_h[NLAYER * 128 * 128];
__device__ __half g_fc_h  [NLAYER * 128 * 512];
__device__ __half g_fc2_h [NLAYER * 512 * 128];

__global__ void cvt_all(const float* __restrict__ qkv, const float* __restrict__ proj,
                        const float* __restrict__ fc,  const float* __restrict__ fc2)
{
    int i = blockIdx.x * 1024 + threadIdx.x;
    if (i < NLAYER*128*384) g_qkv_h [i] = __float2half_rn(qkv[i]);
    if (i < NLAYER*128*128) g_proj_h[i] = __float2half_rn(proj[i]);
    if (i < NLAYER*128*512) g_fc_h  [i] = __float2half_rn(fc[i]);
    if (i < NLAYER*512*128) g_fc2_h [i] = __float2half_rn(fc2[i]);
}

// SMEM layout (floats)
#define OFF_WPE    0                      // 16384
#define OFF_QKVB   (OFF_WPE   + 16384)    // 2304
#define OFF_FCB    (OFF_QKVB  + 2304)     // 3072
#define OFF_PROJB  (OFF_FCB   + 3072)     // 768
#define OFF_FC2B   (OFF_PROJB + 768)      // 768
#define OFF_LN1W   (OFF_FC2B  + 768)      // 768
#define OFF_LN1B   (OFF_LN1W  + 768)
#define OFF_LN2W   (OFF_LN1B  + 768)
#define OFF_LN2B   (OFF_LN2W  + 768)
#define OFF_LNFW   (OFF_LN2B  + 768)      // 128
#define OFF_LNFB   (OFF_LNFW  + 128)
#define OFF_HEADW  (OFF_LNFB  + 128)
#define OFF_WTEW   (OFF_HEADW + 128)      // 256
#define OFF_WTEB   (OFF_WTEW  + 256)      // 128
#define OFF_RS     (OFF_WTEB  + 128)      // 128
#define OFF_XB     (OFF_RS    + 128)      // 128
#define OFF_HB     (OFF_XB    + 128)      // 128
#define OFF_QB     (OFF_HB    + 128)      // 64 (local q, 2 heads)
#define OFF_OB     (OFF_QB    + 64)       // 64 (local o)
#define OFF_KCUR   (OFF_OB    + 64)       // 64
#define OFF_VCUR   (OFF_KCUR  + 64)       // 64
#define OFF_ATT    (OFF_VCUR  + 64)       // 256 (2 heads x 128)
#define OFF_GB     (OFF_ATT   + 256)      // 256 (local fc out)
#define OFF_PROJP  (OFF_GB    + 256)      // 128 (peer proj partial recv)
#define OFF_FC2P   (OFF_PROJP + 128)      // 128 (peer fc2 partial recv)
#define OFF_RED    (OFF_FC2P  + 128)      // 4096
#define OFF_WRED   (OFF_RED   + 4096)     // 32
#define OFF_SCAL   (OFF_WRED  + 32)       // 4
#define SMEM_FLOATS (OFF_SCAL + 4)

#define CLUSTER_SYNC() do { \
    asm volatile("barrier.cluster.arrive.aligned;" ::: "memory"); \
    asm volatile("barrier.cluster.wait.aligned;"  ::: "memory"); } while (0)

__device__ __forceinline__ void st_peer_f32(const float* local_ptr, unsigned peer, float v)
{
    unsigned la = (unsigned)__cvta_generic_to_shared(local_ptr);
    unsigned ra;
    asm volatile("mapa.shared::cluster.u32 %0, %1, %2;" : "=r"(ra) : "r"(la), "r"(peer));
    asm volatile("st.shared::cluster.f32 [%0], %1;" :: "r"(ra), "f"(v) : "memory");
}

__device__ __forceinline__ void block_layernorm(
    const float* __restrict__ in, float* __restrict__ outb,
    const float* __restrict__ w, const float* __restrict__ b,
    float* wred, int tid)
{
    float v = (tid < 128) ? in[tid] : 0.f;
    float s1 = v, s2 = v * v;
    #pragma unroll
    for (int o = 16; o > 0; o >>= 1) {
        s1 += __shfl_xor_sync(0xffffffffu, s1, o);
        s2 += __shfl_xor_sync(0xffffffffu, s2, o);
    }
    if ((tid & 31) == 0) { wred[tid >> 5] = s1; wred[16 + (tid >> 5)] = s2; }
    __syncthreads();
    float m   = (wred[0] + wred[1] + wred[2] + wred[3]) * (1.f / 128.f);
    float ex2 = (wred[16] + wred[17] + wred[18] + wred[19]) * (1.f / 128.f);
    float rstd = rsqrtf(ex2 - m * m + 1e-5f);
    if (tid < 128) outb[tid] = (v - m) * rstd * w[tid] + b[tid];
    __syncthreads();
}

__global__ __launch_bounds__(NTHREADS, 1) __cluster_dims__(2, 1, 1)
void gpt_rollout_kernel(
    const float* __restrict__ data,
    const float* __restrict__ r,
    const float* __restrict__ wte_w,  const float* __restrict__ wte_b,
    const float* __restrict__ wpe,
    const float* __restrict__ ln1_w,  const float* __restrict__ ln1_b,
    const float* __restrict__ ln2_w,  const float* __restrict__ ln2_b,
    const float* __restrict__ qkv_b,
    const float* __restrict__ proj_b,
    const float* __restrict__ fc_b,
    const float* __restrict__ fc2_b,
    const float* __restrict__ lnf_w,  const float* __restrict__ lnf_b,
    const float* __restrict__ head_w, const float* __restrict__ head_b,
    float* __restrict__ out)
{
    extern __shared__ float sm[];
    float* wpe_s   = sm + OFF_WPE;
    float* qkvb_s  = sm + OFF_QKVB;
    float* fcb_s   = sm + OFF_FCB;
    float* projb_s = sm + OFF_PROJB;
    float* fc2b_s  = sm + OFF_FC2B;
    float* ln1w_s  = sm + OFF_LN1W;
    float* ln1b_s  = sm + OFF_LN1B;
    float* ln2w_s  = sm + OFF_LN2W;
    float* ln2b_s  = sm + OFF_LN2B;
    float* lnfw_s  = sm + OFF_LNFW;
    float* lnfb_s  = sm + OFF_LNFB;
    float* headw_s = sm + OFF_HEADW;
    float* wtew_s  = sm + OFF_WTEW;
    float* wteb_s  = sm + OFF_WTEB;
    float* rs      = sm + OFF_RS;
    float* xb      = sm + OFF_XB;
    float* hb      = sm + OFF_HB;
    float* qb      = sm + OFF_QB;     // local q (2 heads = 64 dims)
    float* ob      = sm + OFF_OB;     // local o (64 dims)
    float* kcur    = sm + OFF_KCUR;
    float* vcur    = sm + OFF_VCUR;
    float* att     = sm + OFF_ATT;    // 2 heads x 128
    float* gb      = sm + OFF_GB;     // local fc out (256)
    float* projp   = sm + OFF_PROJP;  // peer proj partial
    float* fc2p    = sm + OFF_FC2P;   // peer fc2 partial
    float* red     = sm + OFF_RED;
    float* wred    = sm + OFF_WRED;
    float* scal    = sm + OFF_SCAL;

    const int b    = blockIdx.x >> 1;
    const unsigned rank = blockIdx.x & 1;   // == cluster_ctarank for (2,1,1)
    const unsigned peer = rank ^ 1;
    const int tid  = threadIdx.x;

    const float p0 = data[b * 2 + 0];
    const float p1 = data[b * 2 + 1];

    // ----- one-time preload of small params (each CTA keeps a full copy) -----
    for (int idx = tid; idx < 16384; idx += NTHREADS) wpe_s[idx]  = wpe[idx];
    for (int idx = tid; idx < 2304;  idx += NTHREADS) qkvb_s[idx] = qkv_b[idx];
    for (int idx = tid; idx < 3072;  idx += NTHREADS) fcb_s[idx]  = fc_b[idx];
    for (int idx = tid; idx < 768;   idx += NTHREADS) {
        projb_s[idx] = proj_b[idx];
        fc2b_s[idx]  = fc2_b[idx];
        ln1w_s[idx]  = ln1_w[idx];
        ln1b_s[idx]  = ln1_b[idx];
        ln2w_s[idx]  = ln2_w[idx];
        ln2b_s[idx]  = ln2_b[idx];
    }
    if (tid < 128) {
        lnfw_s[tid]  = lnf_w[tid];
        lnfb_s[tid]  = lnf_b[tid];
        headw_s[tid] = head_w[tid];
        wteb_s[tid]  = wte_b[tid];
        rs[tid]      = r[b * TH + tid];
    }
    if (tid < 256) wtew_s[tid] = wte_w[tid];
    if (tid == 0) { scal[0] = 0.f; scal[1] = 0.f; scal[2] = head_b[0]; }
    __syncthreads();

    for (int i = 0; i < TH; i++) {
        const float s_cur  = scal[0];
        const float u_prev = scal[1];
        if (rank == 0 && tid == 0) out[b * TH + i] = s_cur;
        const float e = rs[i] - s_cur;

        if (tid < 128) {
            xb[tid] = e * wtew_s[tid] + u_prev * wtew_s[128 + tid]
                      + wteb_s[tid] + wpe_s[i * 128 + tid];
        }
        __syncthreads();

        for (int l = 0; l < NLAYER; l++) {
            float* kbase = g_k + (size_t)(b * NLAYER + l) * DMODEL * TH;
            float* vbase = g_v + (size_t)(b * NLAYER + l) * TH * DMODEL;

            // ----- ln1 (redundant in both CTAs) -----
            block_layernorm(xb, hb, ln1w_s + l * 128, ln1b_s + l * 128, wred, tid);

            // ----- qkv: this CTA's 192 cols (q/k/v dims rank*64..+64).
            //       24 col-groups(x8) * 16 K-segs(8 rows) = 384 thr, 8 loads -----
            if (tid < 384) {
                const int s = tid / 24, g = tid % 24;
                const int chunk = g >> 3, gi = g & 7;       // chunk: 0=q,1=k,2=v
                const int gcol = chunk * 128 + (int)rank * 64 + gi * 8;
                const __half* W = g_qkv_h + l * (128 * 384) + (s * 8) * 384 + gcol;
                const float* hp = hb + s * 8;
                float a0=0,a1=0,a2=0,a3=0,a4=0,a5=0,a6=0,a7=0;
                #pragma unroll
                for (int d = 0; d < 8; d++) {
                    float h = hp[d];
                    uint4 wv = *(const uint4*)(W + d * 384);
                    const __half2* h2 = reinterpret_cast<const __half2*>(&wv);
                    float2 f0 = __half22float2(h2[0]);
                    float2 f1 = __half22float2(h2[1]);
                    float2 f2 = __half22float2(h2[2]);
                    float2 f3 = __half22float2(h2[3]);
                    a0 += h*f0.x; a1 += h*f0.y; a2 += h*f1.x; a3 += h*f1.y;
                    a4 += h*f2.x; a5 += h*f2.y; a6 += h*f3.x; a7 += h*f3.y;
                }
                float4* rp = (float4*)(red + s * 192 + (chunk * 64 + gi * 8));
                rp[0] = make_float4(a0, a1, a2, a3);
                rp[1] = make_float4(a4, a5, a6, a7);
            }
            __syncthreads();

            // ----- qkv reduce: local col c in [0,192) -----
            if (tid < 192) {
                const int chunk = tid >> 6, cw = tid & 63;
                const int gcol = chunk * 128 + (int)rank * 64 + cw;
                float acc = qkvb_s[l * 384 + gcol];
                #pragma unroll
                for (int s = 0; s < 16; s++) acc += red[s * 192 + tid];
                if (chunk == 0)      qb[cw] = acc;
                else if (chunk == 1) { kbase[((int)rank * 64 + cw) * TH + i] = acc; kcur[cw] = acc; }
                else                 { vbase[i * DMODEL + (int)rank * 64 + cw] = acc; vcur[cw] = acc; }
            }
            __syncthreads();

            // ----- attention logits: 2 local heads x 128 keys = 256 thr -----
            const int hl = (tid >> 7) & 1;     // local head 0/1
            const int jj = tid & 127;
            float logit = -3.0e38f;
            if (tid < 256) {
                if (jj < i) {
                    const float* kp = kbase + ((int)rank * 64 + hl * 32) * TH + jj;
                    float dot = 0.f;
                    #pragma unroll
                    for (int d = 0; d < 32; d += 4) {
                        float4 qv = *(const float4*)(qb + hl * 32 + d);
                        dot += qv.x * kp[(d + 0) * TH] + qv.y * kp[(d + 1) * TH]
                             + qv.z * kp[(d + 2) * TH] + qv.w * kp[(d + 3) * TH];
                    }
                    logit = dot * 0.17677669529663689f;
                } else if (jj == i) {
                    const float* kp = kcur + hl * 32;
                    float dot = 0.f;
                    #pragma unroll
                    for (int d = 0; d < 32; d += 4) {
                        float4 qv = *(const float4*)(qb + hl * 32 + d);
                        dot += qv.x * kp[d + 0] + qv.y * kp[d + 1]
                             + qv.z * kp[d + 2] + qv.w * kp[d + 3];
                    }
                    logit = dot * 0.17677669529663689f;
                }
            }

            // ----- softmax over this CTA's 2 heads (warps 0-7 active) -----
            {
                float mx = logit;
                #pragma unroll
                for (int o = 16; o > 0; o >>= 1)
                    mx = fmaxf(mx, __shfl_xor_sync(0xffffffffu, mx, o));
                if (tid < 256 && (tid & 31) == 0) wred[tid >> 5] = mx;
                __syncthreads();
                float p = 0.f;
                if (tid < 256) {
                    float hmax = fmaxf(fmaxf(wred[hl * 4 + 0], wred[hl * 4 + 1]),
                                       fmaxf(wred[hl * 4 + 2], wred[hl * 4 + 3]));
                    p = (jj <= i) ? expf(logit - hmax) : 0.f;
                }
                float ssum = p;
                #pragma unroll
                for (int o = 16; o > 0; o >>= 1)
                    ssum += __shfl_xor_sync(0xffffffffu, ssum, o);
                if (tid < 256 && (tid & 31) == 0) wred[16 + (tid >> 5)] = ssum;
                __syncthreads();
                if (tid < 256) {
                    float hsum = wred[16 + hl * 4 + 0] + wred[16 + hl * 4 + 1]
                               + wred[16 + hl * 4 + 2] + wred[16 + hl * 4 + 3];
                    att[hl * 128 + jj] = p / hsum;
                }
            }
            __syncthreads();

            // ----- o = att @ V : local 64 dims, j-split x8 (16 j each) -----
            {
                const int s8 = tid >> 6, dl = tid & 63;
                const int j0 = s8 * 16;
                const float* vp = vbase + (int)rank * 64 + dl;
                const float* ap = att + (dl >> 5) * 128;
                float a0=0.f, a1=0.f, a2=0.f, a3=0.f;
                #pragma unroll
                for (int t = 0; t < 16; t += 4) {
                    int j = j0 + t;
                    float v0 = (j + 0 < i) ? vp[(j + 0) * DMODEL] : ((j + 0 == i) ? vcur[dl] : 0.f);
                    float v1 = (j + 1 < i) ? vp[(j + 1) * DMODEL] : ((j + 1 == i) ? vcur[dl] : 0.f);
                    float v2 = (j + 2 < i) ? vp[(j + 2) * DMODEL] : ((j + 2 == i) ? vcur[dl] : 0.f);
                    float v3 = (j + 3 < i) ? vp[(j + 3) * DMODEL] : ((j + 3 == i) ? vcur[dl] : 0.f);
                    a0 += ap[j + 0] * v0;
                    a1 += ap[j + 1] * v1;
                    a2 += ap[j + 2] * v2;
                    a3 += ap[j + 3] * v3;
                }
                red[s8 * 64 + dl] = (a0 + a1) + (a2 + a3);
            }
            __syncthreads();
            if (tid < 64) {
                float acc = 0.f;
                #pragma unroll
                for (int s = 0; s < 8; s++) acc += red[s * 64 + tid];
                ob[tid] = acc;
            }
            __syncthreads();

            // ----- proj partial: K over local o (64 rows), all 128 cols.
            //       16 col-groups(x8) * 32 K-segs(2 rows) = 512 thr, 2 loads -----
            {
                const int s = tid >> 4, g = tid & 15;
                const __half* W = g_proj_h + l * (128 * 128)
                                + ((int)rank * 64 + s * 2) * 128 + g * 8;
                const float* op = ob + s * 2;
                float a0=0,a1=0,a2=0,a3=0,a4=0,a5=0,a6=0,a7=0;
                #pragma unroll
                for (int d = 0; d < 2; d++) {
                    float o = op[d];
                    uint4 wv = *(const uint4*)(W + d * 128);
                    const __half2* h2 = reinterpret_cast<const __half2*>(&wv);
                    float2 f0 = __half22float2(h2[0]);
                    float2 f1 = __half22float2(h2[1]);
                    float2 f2 = __half22float2(h2[2]);
                    float2 f3 = __half22float2(h2[3]);
                    a0 += o*f0.x; a1 += o*f0.y; a2 += o*f1.x; a3 += o*f1.y;
                    a4 += o*f2.x; a5 += o*f2.y; a6 += o*f3.x; a7 += o*f3.y;
                }
                float4* rp = (float4*)(red + s * 128 + g * 8);
                rp[0] = make_float4(a0, a1, a2, a3);
                rp[1] = make_float4(a4, a5, a6, a7);
            }
            __syncthreads();
            float proj_own = 0.f;
            if (tid < 128) {
                #pragma unroll
                for (int s = 0; s < 32; s++) proj_own += red[s * 128 + tid];
                st_peer_f32(projp + tid, peer, proj_own);   // send to peer's recv buf
            }
            CLUSTER_SYNC();
            if (tid < 128)
                xb[tid] += (proj_own + projp[tid]) + projb_s[l * 128 + tid];
            __syncthreads();

            // ----- ln2 (redundant) -----
            block_layernorm(xb, hb, ln2w_s + l * 128, ln2b_s + l * 128, wred, tid);

            // ----- fc: local 256 cols. 32 col-groups(x8) * 16 K-segs(8) = 512 thr -----
            {
                const int s = tid >> 5, g = tid & 31;
                const __half* W = g_fc_h + l * (128 * 512) + (s * 8) * 512
                                + (int)rank * 256 + g * 8;
                const float* hp = hb + s * 8;
                float a0=0,a1=0,a2=0,a3=0,a4=0,a5=0,a6=0,a7=0;
                #pragma unroll
                for (int d = 0; d < 8; d++) {
                    float h = hp[d];
                    uint4 wv = *(const uint4*)(W + d * 512);
                    const __half2* h2 = reinterpret_cast<const __half2*>(&wv);
                    float2 f0 = __half22float2(h2[0]);
                    float2 f1 = __half22float2(h2[1]);
                    float2 f2 = __half22float2(h2[2]);
                    float2 f3 = __half22float2(h2[3]);
                    a0 += h*f0.x; a1 += h*f0.y; a2 += h*f1.x; a3 += h*f1.y;
                    a4 += h*f2.x; a5 += h*f2.y; a6 += h*f3.x; a7 += h*f3.y;
                }
                float4* rp = (float4*)(red + s * 256 + g * 8);
                rp[0] = make_float4(a0, a1, a2, a3);
                rp[1] = make_float4(a4, a5, a6, a7);
            }
            __syncthreads();
            if (tid < 256) {
                float t = fcb_s[l * 512 + (int)rank * 256 + tid];
                #pragma unroll
                for (int s = 0; s < 16; s++) t += red[s * 256 + tid];
                float inner = 0.7978845608028654f * (t + 0.044715f * t * t * t);
                gb[tid] = 0.5f * t * (1.f + tanhf(inner));
            }
            __syncthreads();

            // ----- fc2 partial: K over local g (256 rows), all 128 cols.
            //       16 col-groups(x8) * 32 K-segs(8 rows) = 512 thr, 8 loads -----
            {
                const int s = tid >> 4, g = tid & 15;
                const __half* W = g_fc2_h + l * (512 * 128)
                                + ((int)rank * 256 + s * 8) * 128 + g * 8;
                const float* gp = gb + s * 8;
                float a0=0,a1=0,a2=0,a3=0,a4=0,a5=0,a6=0,a7=0;
                #pragma unroll
                for (int d = 0; d < 8; d++) {
                    float gv = gp[d];
                    uint4 wv = *(const uint4*)(W + d * 128);
                    const __half2* h2 = reinterpret_cast<const __half2*>(&wv);
                    float2 f0 = __half22float2(h2[0]);
                    float2 f1 = __half22float2(h2[1]);
                    float2 f2 = __half22float2(h2[2]);
                    float2 f3 = __half22float2(h2[3]);
                    a0 += gv*f0.x; a1 += gv*f0.y; a2 += gv*f1.x; a3 += gv*f1.y;
                    a4 += gv*f2.x; a5 += gv*f2.y; a6 += gv*f3.x; a7 += gv*f3.y;
                }
                float4* rp = (float4*)(red + s * 128 + g * 8);
                rp[0] = make_float4(a0, a1, a2, a3);
                rp[1] = make_float4(a4, a5, a6, a7);
            }
            __syncthreads();
            float fc2_own = 0.f;
            if (tid < 128) {
                #pragma unroll
                for (int s = 0; s < 32; s++) fc2_own += red[s * 128 + tid];
                st_peer_f32(fc2p + tid, peer, fc2_own);
            }
            CLUSTER_SYNC();
            if (tid < 128)
                xb[tid] += (fc2_own + fc2p[tid]) + fc2b_s[l * 128 + tid];
            __syncthreads();
        } // layers

        // ----- final LN + head (redundant in both CTAs; identical results) -----
        block_layernorm(xb, hb, lnfw_s, lnfb_s, wred, tid);
        {
            float part = (tid < 128) ? hb[tid] * headw_s[tid] : 0.f;
            #pragma unroll
            for (int o = 16; o > 0; o >>= 1)
                part += __shfl_xor_sync(0xffffffffu, part, o);
            if ((tid & 31) == 0) wred[tid >> 5] = part;
            __syncthreads();
            if (tid == 0) {
                float u = wred[0] + wred[1] + wred[2] + wred[3] + scal[2];
                float sn = s_cur + (-p0 * s_cur + p1 * tanhf(u));
                scal[0] = sn;   // s_{i+1}
                scal[1] = u;    // U[:, i+1]
            }
            __syncthreads();
        }
    } // steps
}

extern "C" void kernel_launch(void* const* d_in, const int* in_sizes, int n_in,
                              void* d_out, int out_size)
{
    (void)in_sizes; (void)n_in; (void)out_size;

    cvt_all<<<(NLAYER*128*512 + 1023)/1024, 1024>>>(
        (const float*)d_in[9], (const float*)d_in[11],
        (const float*)d_in[13], (const float*)d_in[15]);

    const size_t smem_bytes = (size_t)SMEM_FLOATS * sizeof(float);
    cudaFuncSetAttribute(gpt_rollout_kernel,
                         cudaFuncAttributeMaxDynamicSharedMemorySize,
                         (int)smem_bytes);
    gpt_rollout_kernel<<<BATCH * 2, NTHREADS, smem_bytes>>>(
        (const float*)d_in[0],   // data
        (const float*)d_in[1],   // r
        (const float*)d_in[2],   // wte_w
        (const float*)d_in[3],   // wte_b
        (const float*)d_in[4],   // wpe
        (const float*)d_in[5],   // ln1_w
        (const float*)d_in[6],   // ln1_b
        (const float*)d_in[7],   // ln2_w
        (const float*)d_in[8],   // ln2_b
        (const float*)d_in[10],  // qkv_b
        (const float*)d_in[12],  // attn_proj_b
        (const float*)d_in[14],  // fc_b
        (const float*)d_in[16],  // fc2_b
        (const float*)d_in[17],  // lnf_w
        (const float*)d_in[18],  // lnf_b
        (const float*)d_in[19],  // head_w
        (const float*)d_in[20],  // head_b
        (float*)d_out);
}

// round 17
// speedup vs baseline: 1.5990x; 1.0491x over previous
#include <cuda_runtime.h>
#include <cuda_fp16.h>
#include <math.h>

// GPTClosedLoop: 128-step closed-loop rollout of a tiny GPT.
// B=32, T_H=128, NR=1, L=6, D=128, H=4, DH=32.
//
// Round 16: 2-CTA cluster per batch (R14) + cp.async SMEM double-staging of
// qkv/proj/fc weights one layer ahead (LDGSTS -> no register pressure, no
// exposed L2 wave). fc2 remains direct LDG. Arithmetic identical to R14.

#define BATCH    32
#define TH       128
#define DMODEL   128
#define NLAYER   6
#define NTHREADS 512

// KV cache: K [b][l][dim][token], V [b][l][token][dim]  (dims split across ranks)
__device__ float g_k[BATCH * NLAYER * DMODEL * TH];
__device__ float g_v[BATCH * NLAYER * TH * DMODEL];

// fp16 weight stages. qkv/fc are pre-sliced per cluster rank for flat staging:
// g_qkv_r[l][rank][row 128][192 local cols], g_fc_r[l][rank][row 128][256 local cols]
__device__ __half g_qkv_r [NLAYER * 2 * 128 * 192];
__device__ __half g_proj_h[NLAYER * 128 * 128];
__device__ __half g_fc_r  [NLAYER * 2 * 128 * 256];
__device__ __half g_fc2_h [NLAYER * 512 * 128];

__global__ void cvt_all(const float* __restrict__ qkv, const float* __restrict__ proj,
                        const float* __restrict__ fc,  const float* __restrict__ fc2)
{
    int i = blockIdx.x * 1024 + threadIdx.x;
    if (i < NLAYER*2*128*192) {          // qkv rank-sliced
        int l = i / 49152, rem = i % 49152;
        int rank = rem / 24576; rem %= 24576;
        int row = rem / 192, lc = rem % 192;
        int chunk = lc / 64, cw = lc % 64;
        g_qkv_r[i] = __float2half_rn(qkv[(l*128 + row)*384 + chunk*128 + rank*64 + cw]);
    }
    if (i < NLAYER*128*128) g_proj_h[i] = __float2half_rn(proj[i]);
    if (i < NLAYER*2*128*256) {          // fc rank-sliced
        int l = i / 65536, rem = i % 65536;
        int rank = rem / 32768; rem %= 32768;
        int row = rem / 256, lc = rem % 256;
        g_fc_r[i] = __float2half_rn(fc[(l*128 + row)*512 + rank*256 + lc]);
    }
    if (i < NLAYER*512*128) g_fc2_h[i] = __float2half_rn(fc2[i]);
}

// SMEM layout (floats)
#define OFF_QKVS  0                       // 12288 (48KB qkv stage)
#define OFF_PROJS (OFF_QKVS  + 12288)     // 4096  (16KB proj stage)
#define OFF_FCS   (OFF_PROJS + 4096)      // 16384 (64KB fc stage)
#define OFF_QKVB  (OFF_FCS   + 16384)     // 2304
#define OFF_FCB   (OFF_QKVB  + 2304)      // 3072
#define OFF_PROJB (OFF_FCB   + 3072)      // 768
#define OFF_FC2B  (OFF_PROJB + 768)
#define OFF_LN1W  (OFF_FC2B  + 768)
#define OFF_LN1B  (OFF_LN1W  + 768)
#define OFF_LN2W  (OFF_LN1B  + 768)
#define OFF_LN2B  (OFF_LN2W  + 768)
#define OFF_LNFW  (OFF_LN2B  + 768)       // 128
#define OFF_LNFB  (OFF_LNFW  + 128)
#define OFF_HEADW (OFF_LNFB  + 128)
#define OFF_WTEW  (OFF_HEADW + 128)       // 256
#define OFF_WTEB  (OFF_WTEW  + 256)       // 128
#define OFF_RS    (OFF_WTEB  + 128)       // 128
#define OFF_XB    (OFF_RS    + 128)       // 128
#define OFF_HB    (OFF_XB    + 128)       // 128
#define OFF_QB    (OFF_HB    + 128)       // 64
#define OFF_OB    (OFF_QB    + 64)        // 64
#define OFF_KCUR  (OFF_OB    + 64)        // 64
#define OFF_VCUR  (OFF_KCUR  + 64)        // 64
#define OFF_ATT   (OFF_VCUR  + 64)        // 256
#define OFF_GB    (OFF_ATT   + 256)       // 256
#define OFF_PROJP (OFF_GB    + 256)       // 128
#define OFF_FC2P  (OFF_PROJP + 128)       // 128
#define OFF_RED   (OFF_FC2P  + 128)       // 4096
#define OFF_WRED  (OFF_RED   + 4096)      // 32
#define OFF_SCAL  (OFF_WRED  + 32)        // 4
#define SMEM_FLOATS (OFF_SCAL + 4)        // 49060 floats = 196240 B

#define CLUSTER_SYNC() do { \
    asm volatile("barrier.cluster.arrive.aligned;" ::: "memory"); \
    asm volatile("barrier.cluster.wait.aligned;"  ::: "memory"); } while (0)

#define CP_COMMIT() asm volatile("cp.async.commit_group;" ::: "memory")
#define CP_WAIT2()  asm volatile("cp.async.wait_group 2;" ::: "memory")

__device__ __forceinline__ void cp16(void* dst_smem, const void* src_g)
{
    unsigned d = (unsigned)__cvta_generic_to_shared(dst_smem);
    asm volatile("cp.async.cg.shared.global [%0], [%1], 16;"
                 :: "r"(d), "l"(src_g) : "memory");
}

__device__ __forceinline__ void st_peer_f32(const float* local_ptr, unsigned peer, float v)
{
    unsigned la = (unsigned)__cvta_generic_to_shared(local_ptr);
    unsigned ra;
    asm volatile("mapa.shared::cluster.u32 %0, %1, %2;" : "=r"(ra) : "r"(la), "r"(peer));
    asm volatile("st.shared::cluster.f32 [%0], %1;" :: "r"(ra), "f"(v) : "memory");
}

__device__ __forceinline__ void block_layernorm(
    const float* __restrict__ in, float* __restrict__ outb,
    const float* __restrict__ w, const float* __restrict__ b,
    float* wred, int tid)
{
    float v = (tid < 128) ? in[tid] : 0.f;
    float s1 = v, s2 = v * v;
    #pragma unroll
    for (int o = 16; o > 0; o >>= 1) {
        s1 += __shfl_xor_sync(0xffffffffu, s1, o);
        s2 += __shfl_xor_sync(0xffffffffu, s2, o);
    }
    if ((tid & 31) == 0) { wred[tid >> 5] = s1; wred[16 + (tid >> 5)] = s2; }
    __syncthreads();
    float m   = (wred[0] + wred[1] + wred[2] + wred[3]) * (1.f / 128.f);
    float ex2 = (wred[16] + wred[17] + wred[18] + wred[19]) * (1.f / 128.f);
    float rstd = rsqrtf(ex2 - m * m + 1e-5f);
    if (tid < 128) outb[tid] = (v - m) * rstd * w[tid] + b[tid];
    __syncthreads();
}

__global__ __launch_bounds__(NTHREADS, 1) __cluster_dims__(2, 1, 1)
void gpt_rollout_kernel(
    const float* __restrict__ data,
    const float* __restrict__ r,
    const float* __restrict__ wte_w,  const float* __restrict__ wte_b,
    const float* __restrict__ wpe,
    const float* __restrict__ ln1_w,  const float* __restrict__ ln1_b,
    const float* __restrict__ ln2_w,  const float* __restrict__ ln2_b,
    const float* __restrict__ qkv_b,
    const float* __restrict__ proj_b,
    const float* __restrict__ fc_b,
    const float* __restrict__ fc2_b,
    const float* __restrict__ lnf_w,  const float* __restrict__ lnf_b,
    const float* __restrict__ head_w, const float* __restrict__ head_b,
    float* __restrict__ out)
{
    extern __shared__ float sm[];
    __half* qkvs   = (__half*)(sm + OFF_QKVS);
    __half* projs  = (__half*)(sm + OFF_PROJS);
    __half* fcs    = (__half*)(sm + OFF_FCS);
    float* qkvb_s  = sm + OFF_QKVB;
    float* fcb_s   = sm + OFF_FCB;
    float* projb_s = sm + OFF_PROJB;
    float* fc2b_s  = sm + OFF_FC2B;
    float* ln1w_s  = sm + OFF_LN1W;
    float* ln1b_s  = sm + OFF_LN1B;
    float* ln2w_s  = sm + OFF_LN2W;
    float* ln2b_s  = sm + OFF_LN2B;
    float* lnfw_s  = sm + OFF_LNFW;
    float* lnfb_s  = sm + OFF_LNFB;
    float* headw_s = sm + OFF_HEADW;
    float* wtew_s  = sm + OFF_WTEW;
    float* wteb_s  = sm + OFF_WTEB;
    float* rs      = sm + OFF_RS;
    float* xb      = sm + OFF_XB;
    float* hb      = sm + OFF_HB;
    float* qb      = sm + OFF_QB;
    float* ob      = sm + OFF_OB;
    float* kcur    = sm + OFF_KCUR;
    float* vcur    = sm + OFF_VCUR;
    float* att     = sm + OFF_ATT;
    float* gb      = sm + OFF_GB;
    float* projp   = sm + OFF_PROJP;
    float* fc2p    = sm + OFF_FC2P;
    float* red     = sm + OFF_RED;
    float* wred    = sm + OFF_WRED;
    float* scal    = sm + OFF_SCAL;

    const int b    = blockIdx.x >> 1;
    const unsigned rank = blockIdx.x & 1;
    const unsigned peer = rank ^ 1;
    const int tid  = threadIdx.x;

    const float p0 = data[b * 2 + 0];
    const float p1 = data[b * 2 + 1];

    // ----- one-time preload of small params -----
    for (int idx = tid; idx < 2304; idx += NTHREADS) qkvb_s[idx] = qkv_b[idx];
    for (int idx = tid; idx < 3072; idx += NTHREADS) fcb_s[idx]  = fc_b[idx];
    for (int idx = tid; idx < 768;  idx += NTHREADS) {
        projb_s[idx] = proj_b[idx];
        fc2b_s[idx]  = fc2_b[idx];
        ln1w_s[idx]  = ln1_w[idx];
        ln1b_s[idx]  = ln1_b[idx];
        ln2w_s[idx]  = ln2_w[idx];
        ln2b_s[idx]  = ln2_b[idx];
    }
    if (tid < 128) {
        lnfw_s[tid]  = lnf_w[tid];
        lnfb_s[tid]  = lnf_b[tid];
        headw_s[tid] = head_w[tid];
        wteb_s[tid]  = wte_b[tid];
        rs[tid]      = r[b * TH + tid];
    }
    if (tid < 256) wtew_s[tid] = wte_w[tid];
    if (tid == 0) { scal[0] = 0.f; scal[1] = 0.f; scal[2] = head_b[0]; }
    __syncthreads();

    // ----- prime layer-0 weight stages (groups cycle: qkv, proj, fc) -----
    {
        const __half* src = g_qkv_r + ((0*2 + rank) * 24576);
        #pragma unroll
        for (int k = 0; k < 6; k++) { int c = tid + k*512; cp16(qkvs + c*8, src + c*8); }
        CP_COMMIT();
        const __half* srcp = g_proj_h + (0*128 + (int)rank*64) * 128;
        #pragma unroll
        for (int k = 0; k < 2; k++) { int c = tid + k*512; cp16(projs + c*8, srcp + c*8); }
        CP_COMMIT();
        const __half* srcf = g_fc_r + ((0*2 + rank) * 32768);
        #pragma unroll
        for (int k = 0; k < 8; k++) { int c = tid + k*512; cp16(fcs + c*8, srcf + c*8); }
        CP_COMMIT();
    }

    for (int i = 0; i < TH; i++) {
        const float s_cur  = scal[0];
        const float u_prev = scal[1];
        if (rank == 0 && tid == 0) out[b * TH + i] = s_cur;
        const float e = rs[i] - s_cur;

        if (tid < 128) {
            xb[tid] = e * wtew_s[tid] + u_prev * wtew_s[128 + tid]
                      + wteb_s[tid] + wpe[i * 128 + tid];
        }
        __syncthreads();

        for (int l = 0; l < NLAYER; l++) {
            const int lnext = (l + 1) % NLAYER;
            float* kbase = g_k + (size_t)(b * NLAYER + l) * DMODEL * TH;
            float* vbase = g_v + (size_t)(b * NLAYER + l) * TH * DMODEL;

            // qkv stage ready? (wait is ~free: committed a full layer ago)
            CP_WAIT2();
            // ----- ln1 (its internal barriers publish the staged data) -----
            block_layernorm(xb, hb, ln1w_s + l * 128, ln1b_s + l * 128, wred, tid);

            // ----- qkv FMA from SMEM stage: 24 col-grp(x8) * 16 K-segs(8 rows) -----
            if (tid < 384) {
                const int s = tid / 24, g = tid % 24;
                const int chunk = g >> 3, gi = g & 7;
                const __half* W = qkvs + (s * 8) * 192 + chunk * 64 + gi * 8;
                const float* hp = hb + s * 8;
                float a0=0,a1=0,a2=0,a3=0,a4=0,a5=0,a6=0,a7=0;
                #pragma unroll
                for (int d = 0; d < 8; d++) {
                    float h = hp[d];
                    uint4 wv = *(const uint4*)(W + d * 192);
                    const __half2* h2 = reinterpret_cast<const __half2*>(&wv);
                    float2 f0 = __half22float2(h2[0]);
                    float2 f1 = __half22float2(h2[1]);
                    float2 f2 = __half22float2(h2[2]);
                    float2 f3 = __half22float2(h2[3]);
                    a0 += h*f0.x; a1 += h*f0.y; a2 += h*f1.x; a3 += h*f1.y;
                    a4 += h*f2.x; a5 += h*f2.y; a6 += h*f3.x; a7 += h*f3.y;
                }
                float4* rp = (float4*)(red + s * 192 + (chunk * 64 + gi * 8));
                rp[0] = make_float4(a0, a1, a2, a3);
                rp[1] = make_float4(a4, a5, a6, a7);
            }
            __syncthreads();

            // issue qkv stage for next layer (buffer free now)
            {
                const __half* src = g_qkv_r + ((lnext*2 + (int)rank) * 24576);
                #pragma unroll
                for (int k = 0; k < 6; k++) { int c = tid + k*512; cp16(qkvs + c*8, src + c*8); }
                CP_COMMIT();
            }

            // ----- qkv reduce: local col c in [0,192) -----
            if (tid < 192) {
                const int chunk = tid >> 6, cw = tid & 63;
                const int gcol = chunk * 128 + (int)rank * 64 + cw;
                float acc = qkvb_s[l * 384 + gcol];
                #pragma unroll
                for (int s = 0; s < 16; s++) acc += red[s * 192 + tid];
                if (chunk == 0)      qb[cw] = acc;
                else if (chunk == 1) { kbase[((int)rank * 64 + cw) * TH + i] = acc; kcur[cw] = acc; }
                else                 { vbase[i * DMODEL + (int)rank * 64 + cw] = acc; vcur[cw] = acc; }
            }
            __syncthreads();

            // ----- attention logits: 2 local heads x 128 keys -----
            const int hl = (tid >> 7) & 1;
            const int jj = tid & 127;
            float logit = -3.0e38f;
            if (tid < 256) {
                if (jj < i) {
                    const float* kp = kbase + ((int)rank * 64 + hl * 32) * TH + jj;
                    float dot = 0.f;
                    #pragma unroll
                    for (int d = 0; d < 32; d += 4) {
                        float4 qv = *(const float4*)(qb + hl * 32 + d);
                        dot += qv.x * kp[(d + 0) * TH] + qv.y * kp[(d + 1) * TH]
                             + qv.z * kp[(d + 2) * TH] + qv.w * kp[(d + 3) * TH];
                    }
                    logit = dot * 0.17677669529663689f;
                } else if (jj == i) {
                    const float* kp = kcur + hl * 32;
                    float dot = 0.f;
                    #pragma unroll
                    for (int d = 0; d < 32; d += 4) {
                        float4 qv = *(const float4*)(qb + hl * 32 + d);
                        dot += qv.x * kp[d + 0] + qv.y * kp[d + 1]
                             + qv.z * kp[d + 2] + qv.w * kp[d + 3];
                    }
                    logit = dot * 0.17677669529663689f;
                }
            }

            // ----- softmax over 2 local heads -----
            {
                float mx = logit;
                #pragma unroll
                for (int o = 16; o > 0; o >>= 1)
                    mx = fmaxf(mx, __shfl_xor_sync(0xffffffffu, mx, o));
                if (tid < 256 && (tid & 31) == 0) wred[tid >> 5] = mx;
                __syncthreads();
                float p = 0.f;
                if (tid < 256) {
                    float hmax = fmaxf(fmaxf(wred[hl * 4 + 0], wred[hl * 4 + 1]),
                                       fmaxf(wred[hl * 4 + 2], wred[hl * 4 + 3]));
                    p = (jj <= i) ? expf(logit - hmax) : 0.f;
                }
                float ssum = p;
                #pragma unroll
                for (int o = 16; o > 0; o >>= 1)
                    ssum += __shfl_xor_sync(0xffffffffu, ssum, o);
                if (tid < 256 && (tid & 31) == 0) wred[16 + (tid >> 5)] = ssum;
                __syncthreads();
                if (tid < 256) {
                    float hsum = wred[16 + hl * 4 + 0] + wred[16 + hl * 4 + 1]
                               + wred[16 + hl * 4 + 2] + wred[16 + hl * 4 + 3];
                    att[hl * 128 + jj] = p / hsum;
                }
            }
            __syncthreads();

            // ----- o = att @ V : local 64 dims, j-split x8 -----
            {
                const int s8 = tid >> 6, dl = tid & 63;
                const int j0 = s8 * 16;
                const float* vp = vbase + (int)rank * 64 + dl;
                const float* ap = att + (dl >> 5) * 128;
                float a0=0.f, a1=0.f, a2=0.f, a3=0.f;
                #pragma unroll
                for (int t = 0; t < 16; t += 4) {
                    int j = j0 + t;
                    float v0 = (j + 0 < i) ? vp[(j + 0) * DMODEL] : ((j + 0 == i) ? vcur[dl] : 0.f);
                    float v1 = (j + 1 < i) ? vp[(j + 1) * DMODEL] : ((j + 1 == i) ? vcur[dl] : 0.f);
                    float v2 = (j + 2 < i) ? vp[(j + 2) * DMODEL] : ((j + 2 == i) ? vcur[dl] : 0.f);
                    float v3 = (j + 3 < i) ? vp[(j + 3) * DMODEL] : ((j + 3 == i) ? vcur[dl] : 0.f);
                    a0 += ap[j + 0] * v0;
                    a1 += ap[j + 1] * v1;
                    a2 += ap[j + 2] * v2;
                    a3 += ap[j + 3] * v3;
                }
                red[s8 * 64 + dl] = (a0 + a1) + (a2 + a3);
            }
            __syncthreads();
            if (tid < 64) {
                float acc = 0.f;
                #pragma unroll
                for (int s = 0; s < 8; s++) acc += red[s * 64 + tid];
                ob[tid] = acc;
            }
            CP_WAIT2();          // proj stage ready; next barrier publishes it
            __syncthreads();

            // ----- proj FMA from SMEM stage: 16 col-grp(x8) * 32 K-segs(2) -----
            {
                const int s = tid >> 4, g = tid & 15;
                const __half* W = projs + (s * 2) * 128 + g * 8;
                const float* op = ob + s * 2;
                float a0=0,a1=0,a2=0,a3=0,a4=0,a5=0,a6=0,a7=0;
                #pragma unroll
                for (int d = 0; d < 2; d++) {
                    float o = op[d];
                    uint4 wv = *(const uint4*)(W + d * 128);
                    const __half2* h2 = reinterpret_cast<const __half2*>(&wv);
                    float2 f0 = __half22float2(h2[0]);
                    float2 f1 = __half22float2(h2[1]);
                    float2 f2 = __half22float2(h2[2]);
                    float2 f3 = __half22float2(h2[3]);
                    a0 += o*f0.x; a1 += o*f0.y; a2 += o*f1.x; a3 += o*f1.y;
                    a4 += o*f2.x; a5 += o*f2.y; a6 += o*f3.x; a7 += o*f3.y;
                }
                float4* rp = (float4*)(red + s * 128 + g * 8);
                rp[0] = make_float4(a0, a1, a2, a3);
                rp[1] = make_float4(a4, a5, a6, a7);
            }
            __syncthreads();

            // issue proj stage for next layer
            {
                const __half* srcp = g_proj_h + (lnext*128 + (int)rank*64) * 128;
                #pragma unroll
                for (int k = 0; k < 2; k++) { int c = tid + k*512; cp16(projs + c*8, srcp + c*8); }
                CP_COMMIT();
            }

            float proj_own = 0.f;
            if (tid < 128) {
                #pragma unroll
                for (int s = 0; s < 32; s++) proj_own += red[s * 128 + tid];
                st_peer_f32(projp + tid, peer, proj_own);
            }
            CLUSTER_SYNC();
            if (tid < 128)
                xb[tid] += (proj_own + projp[tid]) + projb_s[l * 128 + tid];
            __syncthreads();

            // fc stage ready? then ln2 (its barriers publish it)
            CP_WAIT2();
            block_layernorm(xb, hb, ln2w_s + l * 128, ln2b_s + l * 128, wred, tid);

            // ----- fc FMA from SMEM stage: 32 col-grp(x8) * 16 K-segs(8) -----
            {
                const int s = tid >> 5, g = tid & 31;
                const __half* W = fcs + (s * 8) * 256 + g * 8;
                const float* hp = hb + s * 8;
                float a0=0,a1=0,a2=0,a3=0,a4=0,a5=0,a6=0,a7=0;
                #pragma unroll
                for (int d = 0; d < 8; d++) {
                    float h = hp[d];
                    uint4 wv = *(const uint4*)(W + d * 256);
                    const __half2* h2 = reinterpret_cast<const __half2*>(&wv);
                    float2 f0 = __half22float2(h2[0]);
                    float2 f1 = __half22float2(h2[1]);
                    float2 f2 = __half22float2(h2[2]);
                    float2 f3 = __half22float2(h2[3]);
                    a0 += h*f0.x; a1 += h*f0.y; a2 += h*f1.x; a3 += h*f1.y;
                    a4 += h*f2.x; a5 += h*f2.y; a6 += h*f3.x; a7 += h*f3.y;
                }
                float4* rp = (float4*)(red + s * 256 + g * 8);
                rp[0] = make_float4(a0, a1, a2, a3);
                rp[1] = make_float4(a4, a5, a6, a7);
            }
            __syncthreads();

            // issue fc stage for next layer
            {
                const __half* srcf = g_fc_r + ((lnext*2 + (int)rank) * 32768);
                #pragma unroll
                for (int k = 0; k < 8; k++) { int c = tid + k*512; cp16(fcs + c*8, srcf + c*8); }
                CP_COMMIT();
            }

            if (tid < 256) {
                float t = fcb_s[l * 512 + (int)rank * 256 + tid];
                #pragma unroll
                for (int s = 0; s < 16; s++) t += red[s * 256 + tid];
                float inner = 0.7978845608028654f * (t + 0.044715f * t * t * t);
                gb[tid] = 0.5f * t * (1.f + tanhf(inner));
            }
            __syncthreads();

            // ----- fc2 partial (direct LDG): 16 col-grp(x8) * 32 K-segs(8) -----
            {
                const int s = tid >> 4, g = tid & 15;
                const __half* W = g_fc2_h + l * (512 * 128)
                                + ((int)rank * 256 + s * 8) * 128 + g * 8;
                const float* gp = gb + s * 8;
                float a0=0,a1=0,a2=0,a3=0,a4=0,a5=0,a6=0,a7=0;
                #pragma unroll
                for (int d = 0; d < 8; d++) {
                    float gv = gp[d];
                    uint4 wv = *(const uint4*)(W + d * 128);
                    const __half2* h2 = reinterpret_cast<const __half2*>(&wv);
                    float2 f0 = __half22float2(h2[0]);
                    float2 f1 = __half22float2(h2[1]);
                    float2 f2 = __half22float2(h2[2]);
                    float2 f3 = __half22float2(h2[3]);
                    a0 += gv*f0.x; a1 += gv*f0.y; a2 += gv*f1.x; a3 += gv*f1.y;
                    a4 += gv*f2.x; a5 += gv*f2.y; a6 += gv*f3.x; a7 += gv*f3.y;
                }
                float4* rp = (float4*)(red + s * 128 + g * 8);
                rp[0] = make_float4(a0, a1, a2, a3);
                rp[1] = make_float4(a4, a5, a6, a7);
            }
            __syncthreads();
            float fc2_own = 0.f;
            if (tid < 128) {
                #pragma unroll
                for (int s = 0; s < 32; s++) fc2_own += red[s * 128 + tid];
                st_peer_f32(fc2p + tid, peer, fc2_own);
            }
            CLUSTER_SYNC();
            if (tid < 128)
                xb[tid] += (fc2_own + fc2p[tid]) + fc2b_s[l * 128 + tid];
            __syncthreads();
        } // layers

        // ----- final LN + head (redundant in both CTAs) -----
        block_layernorm(xb, hb, lnfw_s, lnfb_s, wred, tid);
        {
            float part = (tid < 128) ? hb[tid] * headw_s[tid] : 0.f;
            #pragma unroll
            for (int o = 16; o > 0; o >>= 1)
                part += __shfl_xor_sync(0xffffffffu, part, o);
            if ((tid & 31) == 0) wred[tid >> 5] = part;
            __syncthreads();
            if (tid == 0) {
                float u = wred[0] + wred[1] + wred[2] + wred[3] + scal[2];
                float sn = s_cur + (-p0 * s_cur + p1 * tanhf(u));
                scal[0] = sn;
                scal[1] = u;
            }
            __syncthreads();
        }
    } // steps
}

extern "C" void kernel_launch(void* const* d_in, const int* in_sizes, int n_in,
                              void* d_out, int out_size)
{
    (void)in_sizes; (void)n_in; (void)out_size;

    cvt_all<<<(NLAYER*2*128*256 + 1023)/1024, 1024>>>(
        (const float*)d_in[9], (const float*)d_in[11],
        (const float*)d_in[13], (const float*)d_in[15]);

    const size_t smem_bytes = (size_t)SMEM_FLOATS * sizeof(float);
    cudaFuncSetAttribute(gpt_rollout_kernel,
                         cudaFuncAttributeMaxDynamicSharedMemorySize,
                         (int)smem_bytes);
    gpt_rollout_kernel<<<BATCH * 2, NTHREADS, smem_bytes>>>(
        (const float*)d_in[0],   // data
        (const float*)d_in[1],   // r
        (const float*)d_in[2],   // wte_w
        (const float*)d_in[3],   // wte_b
        (const float*)d_in[4],   // wpe
        (const float*)d_in[5],   // ln1_w
        (const float*)d_in[6],   // ln1_b
        (const float*)d_in[7],   // ln2_w
        (const float*)d_in[8],   // ln2_b
        (const float*)d_in[10],  // qkv_b
        (const float*)d_in[12],  // attn_proj_b
        (const float*)d_in[14],  // fc_b
        (const float*)d_in[16],  // fc2_b
        (const float*)d_in[17],  // lnf_w
        (const float*)d_in[18],  // lnf_b
        (const float*)d_in[19],  // head_w
        (const float*)d_in[20],  // head_b
        (float*)d_out);
}